// round 13
// baseline (speedup 1.0000x reference)
#include <cuda_runtime.h>
#include <cuda_bf16.h>
#include <math.h>
#include <stdint.h>

#define SEQ     2048
#define DIM     768
#define NH      12
#define HD      64
#define HIDDEN  2042
#define HIDP    2048
#define N13     4096
#define QKVN    2304
#define VOCAB   32000
#define NL      4
#define THETA   10000.0f
#define ATT_SCALE 0.125f

typedef __nv_bfloat16 bf16;
typedef __nv_bfloat162 bf162;

// ---------------- fp32 scratch ----------------
__device__ float g_h  [SEQ * DIM];
__device__ float g_qkv[SEQ * QKVN];

// ---------------- bf16 hi/lo planes (16B aligned) ----------------
__device__ __align__(16) bf16 g_wqkv_h[NL * QKVN * DIM],  g_wqkv_l[NL * QKVN * DIM];
__device__ __align__(16) bf16 g_wo_h  [NL * DIM * DIM],   g_wo_l  [NL * DIM * DIM];
__device__ __align__(16) bf16 g_w13_h [NL * N13 * DIM],   g_w13_l [NL * N13 * DIM];  // interleaved w1/w3
__device__ __align__(16) bf16 g_w2_h  [NL * DIM * HIDP],  g_w2_l  [NL * DIM * HIDP];
__device__ __align__(16) bf16 g_ow_h  [VOCAB * DIM],      g_ow_l  [VOCAB * DIM];
__device__ __align__(16) bf16 g_xh [SEQ * DIM],  g_xl [SEQ * DIM];
__device__ __align__(16) bf16 g_oh [SEQ * DIM],  g_ol [SEQ * DIM];
__device__ __align__(16) bf16 g_h1h[SEQ * HIDP], g_h1l[SEQ * HIDP];

// ---------------- helpers ----------------
__device__ __forceinline__ void split1(float v, bf16& h, bf16& l) {
    h = __float2bfloat16(v);
    l = __float2bfloat16(v - __bfloat162float(h));
}

__device__ __forceinline__ void store_split4(bf162* dh, bf162* dl, long d2, float4 v) {
    bf16 h0, l0, h1, l1, h2, l2, h3, l3;
    split1(v.x, h0, l0); split1(v.y, h1, l1);
    split1(v.z, h2, l2); split1(v.w, h3, l3);
    dh[d2]     = __halves2bfloat162(h0, h1);
    dh[d2 + 1] = __halves2bfloat162(h2, h3);
    dl[d2]     = __halves2bfloat162(l0, l1);
    dl[d2 + 1] = __halves2bfloat162(l2, l3);
}

__global__ void split4_kernel(const float4* __restrict__ src,
                              bf162* __restrict__ dh, bf162* __restrict__ dl,
                              long n4) {
    long stride = (long)gridDim.x * blockDim.x;
    for (long i = (long)blockIdx.x * blockDim.x + threadIdx.x; i < n4; i += stride)
        store_split4(dh, dl, i * 2, src[i]);
}

__global__ void split_qkv_all(const float4* __restrict__ wq, const float4* __restrict__ wk,
                              const float4* __restrict__ wv,
                              bf162* __restrict__ dh, bf162* __restrict__ dl) {
    const long SEG4 = (long)DIM * DIM / 4;
    long n4 = NL * 3 * SEG4;
    long stride = (long)gridDim.x * blockDim.x;
    for (long i = (long)blockIdx.x * blockDim.x + threadIdx.x; i < n4; i += stride) {
        long seg = i / SEG4;
        int L = (int)(seg / 3), t = (int)(seg % 3);
        long o4 = i - seg * SEG4;
        const float4* src = (t == 0 ? wq : t == 1 ? wk : wv) + L * SEG4 + o4;
        long d4 = ((long)L * QKVN + t * DIM) * (DIM / 4) + o4;
        store_split4(dh, dl, d4 * 2, *src);
    }
}

__global__ void split_w13_all(const float* __restrict__ w1, const float* __restrict__ w3,
                              bf162* __restrict__ dh, bf162* __restrict__ dl) {
    const int D4 = DIM / 4;
    long n4 = (long)NL * N13 * D4;
    long stride = (long)gridDim.x * blockDim.x;
    for (long i = (long)blockIdx.x * blockDim.x + threadIdx.x; i < n4; i += stride) {
        int col4 = (int)(i % D4);
        long rr = i / D4;
        int r = (int)(rr % N13);
        int L = (int)(rr / N13);
        int j = r >> 1, t = r & 1;
        float4 v = make_float4(0.f, 0.f, 0.f, 0.f);
        if (j < HIDDEN) {
            const float* s = (t ? w3 : w1) + ((long)L * HIDDEN + j) * DIM + col4 * 4;
            v = *(const float4*)s;
        }
        store_split4(dh, dl, i * 2, v);
    }
}

__global__ void split2_pad_kernel(const float* __restrict__ src,
                                  bf162* __restrict__ dh, bf162* __restrict__ dl,
                                  int rows, int Ks, int Kd) {
    long n2 = (long)rows * (Kd / 2);
    long stride = (long)gridDim.x * blockDim.x;
    for (long i = (long)blockIdx.x * blockDim.x + threadIdx.x; i < n2; i += stride) {
        int r  = (int)(i / (Kd / 2));
        int c2 = (int)(i - (long)r * (Kd / 2));
        float2 v = make_float2(0.f, 0.f);
        if (c2 * 2 + 1 < Ks)
            v = *reinterpret_cast<const float2*>(src + (long)r * Ks + c2 * 2);
        bf16 h0, l0, h1, l1;
        split1(v.x, h0, l0); split1(v.y, h1, l1);
        dh[i] = __halves2bfloat162(h0, h1);
        dl[i] = __halves2bfloat162(l0, l1);
    }
}

__global__ void embed_kernel(const int* __restrict__ tokens,
                             const float* __restrict__ emb,
                             float* __restrict__ h) {
    int i = blockIdx.x * blockDim.x + threadIdx.x;
    if (i < SEQ * DIM) {
        int s = i / DIM, d = i - s * DIM;
        h[i] = emb[(long)tokens[s] * DIM + d];
    }
}

__global__ void rmsnorm_split_kernel(const float* __restrict__ x,
                                     const float* __restrict__ w,
                                     bf16* __restrict__ yh, bf16* __restrict__ yl) {
    int row = blockIdx.x;
    const float2* xr = (const float2*)(x + (long)row * DIM);
    const float2* w2p = (const float2*)w;
    float ss = 0.f;
    #pragma unroll
    for (int d = threadIdx.x; d < DIM / 2; d += 256) {
        float2 t = xr[d];
        ss += t.x * t.x + t.y * t.y;
    }
    #pragma unroll
    for (int off = 16; off; off >>= 1) ss += __shfl_xor_sync(0xffffffffu, ss, off);
    __shared__ float sred[8];
    if ((threadIdx.x & 31) == 0) sred[threadIdx.x >> 5] = ss;
    __syncthreads();
    __shared__ float s_inv;
    if (threadIdx.x == 0) {
        float tot = 0.f;
        #pragma unroll
        for (int i = 0; i < 8; i++) tot += sred[i];
        s_inv = rsqrtf(tot / (float)DIM + 1e-6f);
    }
    __syncthreads();
    float inv = s_inv;
    bf162* yh2 = (bf162*)(yh + (long)row * DIM);
    bf162* yl2 = (bf162*)(yl + (long)row * DIM);
    for (int d = threadIdx.x; d < DIM / 2; d += 256) {
        float2 t = xr[d], ww = w2p[d];
        float v0 = t.x * inv * ww.x, v1 = t.y * inv * ww.y;
        bf16 h0, l0, h1, l1;
        split1(v0, h0, l0); split1(v1, h1, l1);
        yh2[d] = __halves2bfloat162(h0, h1);
        yl2[d] = __halves2bfloat162(l0, l1);
    }
}

__global__ void rope_kernel(float* __restrict__ qkv) {
    int i = blockIdx.x * blockDim.x + threadIdx.x;
    if (i >= SEQ * NH * (HD / 2)) return;
    int p  = i % (HD / 2);
    int sh = i / (HD / 2);
    int h  = sh % NH;
    int s  = sh / NH;
    float freq = powf(THETA, -(2.0f * (float)p) / (float)HD);
    float ang  = (float)s * freq;
    float c = cosf(ang), sn = sinf(ang);
    long base = (long)s * QKVN + h * HD + 2 * p;
    float a = qkv[base], b = qkv[base + 1];
    qkv[base]     = a * c - b * sn;
    qkv[base + 1] = a * sn + b * c;
    a = qkv[base + DIM]; b = qkv[base + DIM + 1];
    qkv[base + DIM]     = a * c - b * sn;
    qkv[base + DIM + 1] = a * sn + b * c;
}

// ---------------- flash attention (vectorized smem, transposed V) ----------------
#define BQ 16
__global__ __launch_bounds__(32 * BQ)
void attn_kernel(const float* __restrict__ qkv,
                 bf16* __restrict__ ohp, bf16* __restrict__ olp) {
    int h    = blockIdx.y;
    int q0   = blockIdx.x * BQ;
    int warp = threadIdx.x >> 5;
    int lane = threadIdx.x & 31;
    int qi   = q0 + warp;

    // 68-float row stride: rows 16B-aligned (272B), conflict-free float4 access
    __shared__ __align__(16) float Ks[64][68];   // [key][dim]
    __shared__ __align__(16) float Vt[64][68];   // [dim][key]  (transposed)
    __shared__ __align__(16) float Qs[BQ][68];

    Qs[warp][lane]      = qkv[(long)qi * QKVN + h * HD + lane];
    Qs[warp][lane + 32] = qkv[(long)qi * QKVN + h * HD + lane + 32];

    float m = -INFINITY, l = 0.f, o0 = 0.f, o1 = 0.f;
    int kend = q0 + BQ;

    for (int t0 = 0; t0 < kend; t0 += 64) {
        __syncthreads();
        for (int idx = threadIdx.x; idx < 64 * HD; idx += 32 * BQ) {
            int kj = idx >> 6, d = idx & 63;
            long row = (long)(t0 + kj) * QKVN + h * HD + d;
            Ks[kj][d] = qkv[row + DIM];
            Vt[d][kj] = qkv[row + 2 * DIM];
        }
        __syncthreads();

        // QK: float4 loads, 8 fma per d4
        float s0 = 0.f, s1 = 0.f;
        #pragma unroll
        for (int d4 = 0; d4 < HD / 4; d4++) {
            float4 qv = *(const float4*)&Qs[warp][d4 * 4];
            float4 k0 = *(const float4*)&Ks[lane][d4 * 4];
            float4 k1 = *(const float4*)&Ks[lane + 32][d4 * 4];
            s0 = fmaf(qv.x, k0.x, s0); s0 = fmaf(qv.y, k0.y, s0);
            s0 = fmaf(qv.z, k0.z, s0); s0 = fmaf(qv.w, k0.w, s0);
            s1 = fmaf(qv.x, k1.x, s1); s1 = fmaf(qv.y, k1.y, s1);
            s1 = fmaf(qv.z, k1.z, s1); s1 = fmaf(qv.w, k1.w, s1);
        }
        s0 *= ATT_SCALE; s1 *= ATT_SCALE;
        if (t0 + lane      > qi) s0 = -INFINITY;
        if (t0 + lane + 32 > qi) s1 = -INFINITY;

        float mt = fmaxf(s0, s1);
        #pragma unroll
        for (int off = 16; off; off >>= 1)
            mt = fmaxf(mt, __shfl_xor_sync(0xffffffffu, mt, off));
        float mnew  = fmaxf(m, mt);
        float alpha = __expf(m - mnew);
        float p0 = __expf(s0 - mnew);
        float p1 = __expf(s1 - mnew);
        float lsum = p0 + p1;
        #pragma unroll
        for (int off = 16; off; off >>= 1)
            lsum += __shfl_xor_sync(0xffffffffu, lsum, off);
        l = l * alpha + lsum;
        m = mnew;
        o0 *= alpha; o1 *= alpha;

        // PV: transposed V, float4 over keys
        #pragma unroll
        for (int k4 = 0; k4 < 8; k4++) {        // keys 0..31 (p0)
            float4 va = *(const float4*)&Vt[lane][k4 * 4];
            float4 vb = *(const float4*)&Vt[lane + 32][k4 * 4];
            float pa = __shfl_sync(0xffffffffu, p0, k4 * 4 + 0);
            float pb = __shfl_sync(0xffffffffu, p0, k4 * 4 + 1);
            float pc = __shfl_sync(0xffffffffu, p0, k4 * 4 + 2);
            float pd = __shfl_sync(0xffffffffu, p0, k4 * 4 + 3);
            o0 = fmaf(pa, va.x, o0); o0 = fmaf(pb, va.y, o0);
            o0 = fmaf(pc, va.z, o0); o0 = fmaf(pd, va.w, o0);
            o1 = fmaf(pa, vb.x, o1); o1 = fmaf(pb, vb.y, o1);
            o1 = fmaf(pc, vb.z, o1); o1 = fmaf(pd, vb.w, o1);
        }
        #pragma unroll
        for (int k4 = 0; k4 < 8; k4++) {        // keys 32..63 (p1)
            float4 va = *(const float4*)&Vt[lane][32 + k4 * 4];
            float4 vb = *(const float4*)&Vt[lane + 32][32 + k4 * 4];
            float pa = __shfl_sync(0xffffffffu, p1, k4 * 4 + 0);
            float pb = __shfl_sync(0xffffffffu, p1, k4 * 4 + 1);
            float pc = __shfl_sync(0xffffffffu, p1, k4 * 4 + 2);
            float pd = __shfl_sync(0xffffffffu, p1, k4 * 4 + 3);
            o0 = fmaf(pa, va.x, o0); o0 = fmaf(pb, va.y, o0);
            o0 = fmaf(pc, va.z, o0); o0 = fmaf(pd, va.w, o0);
            o1 = fmaf(pa, vb.x, o1); o1 = fmaf(pb, vb.y, o1);
            o1 = fmaf(pc, vb.z, o1); o1 = fmaf(pd, vb.w, o1);
        }
    }
    float inv = 1.f / l;
    float v0 = o0 * inv, v1 = o1 * inv;
    bf16 hh, ll;
    long base = (long)qi * DIM + h * HD;
    split1(v0, hh, ll); ohp[base + lane]      = hh; olp[base + lane]      = ll;
    split1(v1, hh, ll); ohp[base + lane + 32] = hh; olp[base + lane + 32] = ll;
}

// ================= templated bf16x3 mma.sync GEMM, 3-stage, swizzled smem =================
__device__ __forceinline__ void mma_bf16(float* d, const uint32_t* a, const uint32_t* b) {
    asm volatile(
        "mma.sync.aligned.m16n8k16.row.col.f32.bf16.bf16.f32 "
        "{%0,%1,%2,%3}, {%4,%5,%6,%7}, {%8,%9}, {%0,%1,%2,%3};"
        : "+f"(d[0]), "+f"(d[1]), "+f"(d[2]), "+f"(d[3])
        : "r"(a[0]), "r"(a[1]), "r"(a[2]), "r"(a[3]), "r"(b[0]), "r"(b[1]));
}
__device__ __forceinline__ void ldmx4(uint32_t* r, uint32_t addr) {
    asm volatile("ldmatrix.sync.aligned.m8n8.x4.shared.b16 {%0,%1,%2,%3}, [%4];"
                 : "=r"(r[0]), "=r"(r[1]), "=r"(r[2]), "=r"(r[3]) : "r"(addr));
}
__device__ __forceinline__ void cpa16(uint32_t dst, const void* src) {
    asm volatile("cp.async.cg.shared.global [%0], [%1], 16;" :: "r"(dst), "l"(src));
}

template<int BM, int WM, int WN, int THREADS, int MAXB, int K, int EPI>
__global__ __launch_bounds__(THREADS, MAXB)
void gemm_bf3(const bf16* __restrict__ Ah, const bf16* __restrict__ Al,
              const bf16* __restrict__ Bh, const bf16* __restrict__ Bl,
              const float* __restrict__ res, float* __restrict__ C,
              bf16* __restrict__ Eh, bf16* __restrict__ El,
              int N) {
    const int BN = BM;
    const int WARPS_N = BN / WN;
    const int MT = WM / 16;
    const int NT = WN / 8;
    const int PB = BM * 64;
    const int SB = 4 * PB;
    const int KT = K / 32;
    const int CPT = 16 * BM / THREADS;

    extern __shared__ char smc[];
    uint32_t sbase = (uint32_t)__cvta_generic_to_shared(smc);

    int bm = blockIdx.y * BM;
    int bn = blockIdx.x * BN;
    int tid  = threadIdx.x;
    int warp = tid >> 5, lane = tid & 31;
    int wm = (warp / WARPS_N) * WM;
    int wn = (warp % WARPS_N) * WN;
    int g  = lane >> 2, tg = lane & 3;
    int rr = lane & 7, q = lane >> 3;

    int aRowL = wm + rr + 8 * (q & 1);
    int bRowL = wn + rr + 8 * (q >> 1);
    uint32_t aRowOff = (uint32_t)aRowL * 64;
    uint32_t bRowOff = (uint32_t)bRowL * 64;
    uint32_t swA = (uint32_t)((aRowL >> 1) & 3);
    uint32_t swB = (uint32_t)((bRowL >> 1) & 3);
    uint32_t cAk[2], cBk[2];
    #pragma unroll
    for (int ks = 0; ks < 2; ks++) {
        cAk[ks] = ((uint32_t)(2 * ks + (q >> 1)) ^ swA) << 4;
        cBk[ks] = ((uint32_t)(2 * ks + (q & 1))  ^ swB) << 4;
    }

    const bf16* pl[4] = { Ah, Al, Bh, Bl };
    uint32_t dstoff[CPT];
    const bf16* srcb[CPT];
    #pragma unroll
    for (int t = 0; t < CPT; t++) {
        int cid = tid + t * THREADS;
        int p   = cid / (4 * BM);
        int rem = cid - p * (4 * BM);
        int row = rem >> 2, ch = rem & 3;
        dstoff[t] = (uint32_t)p * PB + (uint32_t)row * 64
                  + (((uint32_t)ch ^ (((uint32_t)row >> 1) & 3)) << 4);
        int rowG = ((p < 2) ? bm : bn) + row;
        srcb[t] = pl[p] + (long)rowG * K + ch * 8;
    }

    float acc[MT][NT][4];
    #pragma unroll
    for (int mi = 0; mi < MT; mi++)
        #pragma unroll
        for (int ni = 0; ni < NT; ni++)
            #pragma unroll
            for (int r = 0; r < 4; r++) acc[mi][ni][r] = 0.f;

    auto fill = [&](int s, int k0) {
        uint32_t st = sbase + (uint32_t)s * SB;
        #pragma unroll
        for (int t = 0; t < CPT; t++)
            cpa16(st + dstoff[t], srcb[t] + k0);
        asm volatile("cp.async.commit_group;");
    };

    fill(0, 0);
    fill(1, 32);

    #pragma unroll 3
    for (int kt = 0; kt < KT; kt++) {
        if (kt + 1 < KT) asm volatile("cp.async.wait_group 1;");
        else             asm volatile("cp.async.wait_group 0;");
        __syncthreads();

        if (kt + 2 < KT) fill((kt + 2) % 3, (kt + 2) * 32);

        uint32_t st  = sbase + (uint32_t)(kt % 3) * SB;
        uint32_t pAH = st;
        uint32_t pAL = st + PB;
        uint32_t pBH = st + 2 * PB;
        uint32_t pBL = st + 3 * PB;

        #pragma unroll
        for (int ks = 0; ks < 2; ks++) {
            uint32_t afH[MT][4], bfH[NT][2], bfX[NT][2];
            #pragma unroll
            for (int mi = 0; mi < MT; mi++)
                ldmx4(afH[mi], pAH + aRowOff + (uint32_t)mi * 1024 + cAk[ks]);
            #pragma unroll
            for (int n2 = 0; n2 < NT / 2; n2++) {
                uint32_t t[4];
                ldmx4(t, pBH + bRowOff + (uint32_t)n2 * 1024 + cBk[ks]);
                bfH[2 * n2][0] = t[0]; bfH[2 * n2][1] = t[1];
                bfH[2 * n2 + 1][0] = t[2]; bfH[2 * n2 + 1][1] = t[3];
            }
            #pragma unroll
            for (int mi = 0; mi < MT; mi++)
                #pragma unroll
                for (int ni = 0; ni < NT; ni++)
                    mma_bf16(acc[mi][ni], afH[mi], bfH[ni]);

            #pragma unroll
            for (int n2 = 0; n2 < NT / 2; n2++) {
                uint32_t t[4];
                ldmx4(t, pBL + bRowOff + (uint32_t)n2 * 1024 + cBk[ks]);
                bfX[2 * n2][0] = t[0]; bfX[2 * n2][1] = t[1];
                bfX[2 * n2 + 1][0] = t[2]; bfX[2 * n2 + 1][1] = t[3];
            }
            #pragma unroll
            for (int mi = 0; mi < MT; mi++)
                #pragma unroll
                for (int ni = 0; ni < NT; ni++)
                    mma_bf16(acc[mi][ni], afH[mi], bfX[ni]);

            #pragma unroll
            for (int mi = 0; mi < MT; mi++)
                ldmx4(afH[mi], pAL + aRowOff + (uint32_t)mi * 1024 + cAk[ks]);
            #pragma unroll
            for (int mi = 0; mi < MT; mi++)
                #pragma unroll
                for (int ni = 0; ni < NT; ni++)
                    mma_bf16(acc[mi][ni], afH[mi], bfH[ni]);
        }
    }

    #pragma unroll
    for (int mi = 0; mi < MT; mi++) {
        int row0 = bm + wm + mi * 16 + g;
        #pragma unroll
        for (int ni = 0; ni < NT; ni++) {
            int col = bn + wn + ni * 8 + tg * 2;
            #pragma unroll
            for (int half = 0; half < 2; half++) {
                int row = row0 + half * 8;
                float v0 = acc[mi][ni][half * 2 + 0];
                float v1 = acc[mi][ni][half * 2 + 1];
                if (EPI == 0) {
                    long idx = (long)row * N + col;
                    if (res) { v0 += res[idx]; v1 += res[idx + 1]; }
                    C[idx]     = v0;
                    C[idx + 1] = v1;
                } else {
                    float v = (v0 / (1.f + __expf(-v0))) * v1;
                    bf16 hh, ll; split1(v, hh, ll);
                    long idx = (long)row * (N / 2) + (col >> 1);
                    Eh[idx] = hh;
                    El[idx] = ll;
                }
            }
        }
    }
}

#define GB768      gemm_bf3<128, 64, 32, 256, 2, 768, 0>
#define GB768_SILU gemm_bf3<128, 64, 32, 256, 2, 768, 1>
#define GS768      gemm_bf3< 64, 32, 32, 128, 4, 768, 0>
#define GS2048     gemm_bf3< 64, 32, 32, 128, 4, 2048, 0>
#define SMEM_B  (3 * 4 * 128 * 64)   // 98304
#define SMEM_S  (3 * 4 * 64 * 64)    // 49152

static inline unsigned gblocks(long n, int cap) {
    long b = (n + 255) / 256;
    if (b > cap) b = cap;
    return (unsigned)b;
}

extern "C" void kernel_launch(void* const* d_in, const int* in_sizes, int n_in,
                              void* d_out, int out_size) {
    const int*   tokens   = (const int*)  d_in[0];
    const float* emb      = (const float*)d_in[1];
    const float* wq       = (const float*)d_in[2];
    const float* wk       = (const float*)d_in[3];
    const float* wv       = (const float*)d_in[4];
    const float* wo       = (const float*)d_in[5];
    const float* w1       = (const float*)d_in[6];
    const float* w2       = (const float*)d_in[7];
    const float* w3       = (const float*)d_in[8];
    const float* attn_nw  = (const float*)d_in[9];
    const float* ffn_nw   = (const float*)d_in[10];
    const float* norm_w   = (const float*)d_in[11];
    const float* out_w    = (const float*)d_in[12];
    float* out = (float*)d_out;

    float *h, *qkv;
    cudaGetSymbolAddress((void**)&h,   g_h);
    cudaGetSymbolAddress((void**)&qkv, g_qkv);

    bf16 *wqkvh, *wqkvl, *woh, *wol, *w13h, *w13l, *w2h, *w2l, *owh, *owl;
    bf16 *xh, *xl, *oh, *ol, *h1h, *h1l;
    cudaGetSymbolAddress((void**)&wqkvh, g_wqkv_h); cudaGetSymbolAddress((void**)&wqkvl, g_wqkv_l);
    cudaGetSymbolAddress((void**)&woh,   g_wo_h);   cudaGetSymbolAddress((void**)&wol,   g_wo_l);
    cudaGetSymbolAddress((void**)&w13h,  g_w13_h);  cudaGetSymbolAddress((void**)&w13l,  g_w13_l);
    cudaGetSymbolAddress((void**)&w2h,   g_w2_h);   cudaGetSymbolAddress((void**)&w2l,   g_w2_l);
    cudaGetSymbolAddress((void**)&owh,   g_ow_h);   cudaGetSymbolAddress((void**)&owl,   g_ow_l);
    cudaGetSymbolAddress((void**)&xh,  g_xh);  cudaGetSymbolAddress((void**)&xl,  g_xl);
    cudaGetSymbolAddress((void**)&oh,  g_oh);  cudaGetSymbolAddress((void**)&ol,  g_ol);
    cudaGetSymbolAddress((void**)&h1h, g_h1h); cudaGetSymbolAddress((void**)&h1l, g_h1l);

    cudaFuncSetAttribute(GB768,      cudaFuncAttributeMaxDynamicSharedMemorySize, SMEM_B);
    cudaFuncSetAttribute(GB768_SILU, cudaFuncAttributeMaxDynamicSharedMemorySize, SMEM_B);
    cudaFuncSetAttribute(GS768,      cudaFuncAttributeMaxDynamicSharedMemorySize, SMEM_S);
    cudaFuncSetAttribute(GS2048,     cudaFuncAttributeMaxDynamicSharedMemorySize, SMEM_S);

    // ---- weight conversion: 5 big launches ----
    split_qkv_all<<<gblocks((long)NL * 3 * DIM * DIM / 4, 16384), 256>>>(
        (const float4*)wq, (const float4*)wk, (const float4*)wv,
        (bf162*)wqkvh, (bf162*)wqkvl);
    split4_kernel<<<gblocks((long)NL * DIM * DIM / 4, 16384), 256>>>(
        (const float4*)wo, (bf162*)woh, (bf162*)wol, (long)NL * DIM * DIM / 4);
    split_w13_all<<<gblocks((long)NL * N13 * DIM / 4, 16384), 256>>>(
        w1, w3, (bf162*)w13h, (bf162*)w13l);
    split2_pad_kernel<<<gblocks((long)NL * DIM * HIDP / 2, 16384), 256>>>(
        w2, (bf162*)w2h, (bf162*)w2l, NL * DIM, HIDDEN, HIDP);
    split4_kernel<<<gblocks((long)VOCAB * DIM / 4, 16384), 256>>>(
        (const float4*)out_w, (bf162*)owh, (bf162*)owl, (long)VOCAB * DIM / 4);

    // ---- forward ----
    embed_kernel<<<(SEQ * DIM + 255) / 256, 256>>>(tokens, emb, h);

    for (int L = 0; L < NL; L++) {
        rmsnorm_split_kernel<<<SEQ, 256>>>(h, attn_nw + L * DIM, xh, xl);

        GB768<<<dim3(QKVN / 128, SEQ / 128), 256, SMEM_B>>>(
            xh, xl, wqkvh + (long)L * QKVN * DIM, wqkvl + (long)L * QKVN * DIM,
            nullptr, qkv, nullptr, nullptr, QKVN);

        rope_kernel<<<(SEQ * NH * (HD / 2) + 255) / 256, 256>>>(qkv);
        attn_kernel<<<dim3(SEQ / BQ, NH), 32 * BQ>>>(qkv, oh, ol);

        GS768<<<dim3(DIM / 64, SEQ / 64), 128, SMEM_S>>>(
            oh, ol, woh + (long)L * DIM * DIM, wol + (long)L * DIM * DIM,
            h, h, nullptr, nullptr, DIM);

        rmsnorm_split_kernel<<<SEQ, 256>>>(h, ffn_nw + L * DIM, xh, xl);

        GB768_SILU<<<dim3(N13 / 128, SEQ / 128), 256, SMEM_B>>>(
            xh, xl, w13h + (long)L * N13 * DIM, w13l + (long)L * N13 * DIM,
            nullptr, nullptr, h1h, h1l, N13);

        GS2048<<<dim3(DIM / 64, SEQ / 64), 128, SMEM_S>>>(
            h1h, h1l, w2h + (long)L * DIM * HIDP, w2l + (long)L * DIM * HIDP,
            h, h, nullptr, nullptr, DIM);
    }

    rmsnorm_split_kernel<<<SEQ, 256>>>(h, norm_w, xh, xl);

    GB768<<<dim3(VOCAB / 128, SEQ / 128), 256, SMEM_B>>>(
        xh, xl, owh, owl, nullptr, out, nullptr, nullptr, VOCAB);
}

// round 14
// speedup vs baseline: 1.0024x; 1.0024x over previous
#include <cuda_runtime.h>
#include <cuda_bf16.h>
#include <math.h>
#include <stdint.h>

#define SEQ     2048
#define DIM     768
#define NH      12
#define HD      64
#define HIDDEN  2042
#define HIDP    2048
#define N13     4096
#define QKVN    2304
#define VOCAB   32000
#define NL      4
#define THETA   10000.0f
#define ATT_SCALE 0.125f

typedef __nv_bfloat16 bf16;
typedef __nv_bfloat162 bf162;

// ---------------- fp32 scratch ----------------
__device__ float g_h  [SEQ * DIM];
__device__ float g_qkv[SEQ * QKVN];

// ---------------- bf16 hi/lo planes (16B aligned) ----------------
__device__ __align__(16) bf16 g_wqkv_h[NL * QKVN * DIM],  g_wqkv_l[NL * QKVN * DIM];
__device__ __align__(16) bf16 g_wo_h  [NL * DIM * DIM],   g_wo_l  [NL * DIM * DIM];
__device__ __align__(16) bf16 g_w13_h [NL * N13 * DIM],   g_w13_l [NL * N13 * DIM];  // interleaved w1/w3
__device__ __align__(16) bf16 g_w2_h  [NL * DIM * HIDP],  g_w2_l  [NL * DIM * HIDP];
__device__ __align__(16) bf16 g_ow_h  [VOCAB * DIM],      g_ow_l  [VOCAB * DIM];
__device__ __align__(16) bf16 g_xh [SEQ * DIM],  g_xl [SEQ * DIM];
__device__ __align__(16) bf16 g_oh [SEQ * DIM],  g_ol [SEQ * DIM];
__device__ __align__(16) bf16 g_h1h[SEQ * HIDP], g_h1l[SEQ * HIDP];

// ---------------- helpers ----------------
__device__ __forceinline__ void split1(float v, bf16& h, bf16& l) {
    h = __float2bfloat16(v);
    l = __float2bfloat16(v - __bfloat162float(h));
}

__device__ __forceinline__ void store_split4(bf162* dh, bf162* dl, long d2, float4 v) {
    bf16 h0, l0, h1, l1, h2, l2, h3, l3;
    split1(v.x, h0, l0); split1(v.y, h1, l1);
    split1(v.z, h2, l2); split1(v.w, h3, l3);
    dh[d2]     = __halves2bfloat162(h0, h1);
    dh[d2 + 1] = __halves2bfloat162(h2, h3);
    dl[d2]     = __halves2bfloat162(l0, l1);
    dl[d2 + 1] = __halves2bfloat162(l2, l3);
}

__global__ void split4_kernel(const float4* __restrict__ src,
                              bf162* __restrict__ dh, bf162* __restrict__ dl,
                              long n4) {
    long stride = (long)gridDim.x * blockDim.x;
    for (long i = (long)blockIdx.x * blockDim.x + threadIdx.x; i < n4; i += stride)
        store_split4(dh, dl, i * 2, src[i]);
}

__global__ void split_qkv_all(const float4* __restrict__ wq, const float4* __restrict__ wk,
                              const float4* __restrict__ wv,
                              bf162* __restrict__ dh, bf162* __restrict__ dl) {
    const long SEG4 = (long)DIM * DIM / 4;
    long n4 = NL * 3 * SEG4;
    long stride = (long)gridDim.x * blockDim.x;
    for (long i = (long)blockIdx.x * blockDim.x + threadIdx.x; i < n4; i += stride) {
        long seg = i / SEG4;
        int L = (int)(seg / 3), t = (int)(seg % 3);
        long o4 = i - seg * SEG4;
        const float4* src = (t == 0 ? wq : t == 1 ? wk : wv) + L * SEG4 + o4;
        long d4 = ((long)L * QKVN + t * DIM) * (DIM / 4) + o4;
        store_split4(dh, dl, d4 * 2, *src);
    }
}

__global__ void split_w13_all(const float* __restrict__ w1, const float* __restrict__ w3,
                              bf162* __restrict__ dh, bf162* __restrict__ dl) {
    const int D4 = DIM / 4;
    long n4 = (long)NL * N13 * D4;
    long stride = (long)gridDim.x * blockDim.x;
    for (long i = (long)blockIdx.x * blockDim.x + threadIdx.x; i < n4; i += stride) {
        int col4 = (int)(i % D4);
        long rr = i / D4;
        int r = (int)(rr % N13);
        int L = (int)(rr / N13);
        int j = r >> 1, t = r & 1;
        float4 v = make_float4(0.f, 0.f, 0.f, 0.f);
        if (j < HIDDEN) {
            const float* s = (t ? w3 : w1) + ((long)L * HIDDEN + j) * DIM + col4 * 4;
            v = *(const float4*)s;
        }
        store_split4(dh, dl, i * 2, v);
    }
}

__global__ void split2_pad_kernel(const float* __restrict__ src,
                                  bf162* __restrict__ dh, bf162* __restrict__ dl,
                                  int rows, int Ks, int Kd) {
    long n2 = (long)rows * (Kd / 2);
    long stride = (long)gridDim.x * blockDim.x;
    for (long i = (long)blockIdx.x * blockDim.x + threadIdx.x; i < n2; i += stride) {
        int r  = (int)(i / (Kd / 2));
        int c2 = (int)(i - (long)r * (Kd / 2));
        float2 v = make_float2(0.f, 0.f);
        if (c2 * 2 + 1 < Ks)
            v = *reinterpret_cast<const float2*>(src + (long)r * Ks + c2 * 2);
        bf16 h0, l0, h1, l1;
        split1(v.x, h0, l0); split1(v.y, h1, l1);
        dh[i] = __halves2bfloat162(h0, h1);
        dl[i] = __halves2bfloat162(l0, l1);
    }
}

__global__ void embed_kernel(const int* __restrict__ tokens,
                             const float* __restrict__ emb,
                             float* __restrict__ h) {
    int i = blockIdx.x * blockDim.x + threadIdx.x;
    if (i < SEQ * DIM) {
        int s = i / DIM, d = i - s * DIM;
        h[i] = emb[(long)tokens[s] * DIM + d];
    }
}

__global__ void rmsnorm_split_kernel(const float* __restrict__ x,
                                     const float* __restrict__ w,
                                     bf16* __restrict__ yh, bf16* __restrict__ yl) {
    int row = blockIdx.x;
    const float2* xr = (const float2*)(x + (long)row * DIM);
    const float2* w2p = (const float2*)w;
    float ss = 0.f;
    #pragma unroll
    for (int d = threadIdx.x; d < DIM / 2; d += 256) {
        float2 t = xr[d];
        ss += t.x * t.x + t.y * t.y;
    }
    #pragma unroll
    for (int off = 16; off; off >>= 1) ss += __shfl_xor_sync(0xffffffffu, ss, off);
    __shared__ float sred[8];
    if ((threadIdx.x & 31) == 0) sred[threadIdx.x >> 5] = ss;
    __syncthreads();
    __shared__ float s_inv;
    if (threadIdx.x == 0) {
        float tot = 0.f;
        #pragma unroll
        for (int i = 0; i < 8; i++) tot += sred[i];
        s_inv = rsqrtf(tot / (float)DIM + 1e-6f);
    }
    __syncthreads();
    float inv = s_inv;
    bf162* yh2 = (bf162*)(yh + (long)row * DIM);
    bf162* yl2 = (bf162*)(yl + (long)row * DIM);
    for (int d = threadIdx.x; d < DIM / 2; d += 256) {
        float2 t = xr[d], ww = w2p[d];
        float v0 = t.x * inv * ww.x, v1 = t.y * inv * ww.y;
        bf16 h0, l0, h1, l1;
        split1(v0, h0, l0); split1(v1, h1, l1);
        yh2[d] = __halves2bfloat162(h0, h1);
        yl2[d] = __halves2bfloat162(l0, l1);
    }
}

__global__ void rope_kernel(float* __restrict__ qkv) {
    int i = blockIdx.x * blockDim.x + threadIdx.x;
    if (i >= SEQ * NH * (HD / 2)) return;
    int p  = i % (HD / 2);
    int sh = i / (HD / 2);
    int h  = sh % NH;
    int s  = sh / NH;
    float freq = powf(THETA, -(2.0f * (float)p) / (float)HD);
    float ang  = (float)s * freq;
    float c = cosf(ang), sn = sinf(ang);
    long base = (long)s * QKVN + h * HD + 2 * p;
    float a = qkv[base], b = qkv[base + 1];
    qkv[base]     = a * c - b * sn;
    qkv[base + 1] = a * sn + b * c;
    a = qkv[base + DIM]; b = qkv[base + DIM + 1];
    qkv[base + DIM]     = a * c - b * sn;
    qkv[base + DIM + 1] = a * sn + b * c;
}

// ---------------- flash attention (R12 form, BQ=32 for halved K/V traffic) ----------------
#define BQ 32
__global__ __launch_bounds__(32 * BQ)
void attn_kernel(const float* __restrict__ qkv,
                 bf16* __restrict__ ohp, bf16* __restrict__ olp) {
    int h    = blockIdx.y;
    int q0   = blockIdx.x * BQ;
    int warp = threadIdx.x >> 5;
    int lane = threadIdx.x & 31;
    int qi   = q0 + warp;

    __shared__ float Ks[64][HD + 1];
    __shared__ float Vs[64][HD + 1];
    __shared__ float Qs[BQ][HD];

    Qs[warp][lane]      = qkv[(long)qi * QKVN + h * HD + lane];
    Qs[warp][lane + 32] = qkv[(long)qi * QKVN + h * HD + lane + 32];

    float m = -INFINITY, l = 0.f, o0 = 0.f, o1 = 0.f;
    int kend = q0 + BQ;

    for (int t0 = 0; t0 < kend; t0 += 64) {
        __syncthreads();
        for (int idx = threadIdx.x; idx < 64 * HD; idx += 32 * BQ) {
            int kj = idx >> 6, d = idx & 63;
            long row = (long)(t0 + kj) * QKVN + h * HD + d;
            Ks[kj][d] = qkv[row + DIM];
            Vs[kj][d] = qkv[row + 2 * DIM];
        }
        __syncthreads();

        float s0 = 0.f, s1 = 0.f;
        #pragma unroll
        for (int d = 0; d < HD; d++) {
            float qd = Qs[warp][d];
            s0 = fmaf(qd, Ks[lane][d],      s0);
            s1 = fmaf(qd, Ks[lane + 32][d], s1);
        }
        s0 *= ATT_SCALE; s1 *= ATT_SCALE;
        if (t0 + lane      > qi) s0 = -INFINITY;
        if (t0 + lane + 32 > qi) s1 = -INFINITY;

        float mt = fmaxf(s0, s1);
        #pragma unroll
        for (int off = 16; off; off >>= 1)
            mt = fmaxf(mt, __shfl_xor_sync(0xffffffffu, mt, off));
        float mnew  = fmaxf(m, mt);
        float alpha = __expf(m - mnew);
        float p0 = __expf(s0 - mnew);
        float p1 = __expf(s1 - mnew);
        float lsum = p0 + p1;
        #pragma unroll
        for (int off = 16; off; off >>= 1)
            lsum += __shfl_xor_sync(0xffffffffu, lsum, off);
        l = l * alpha + lsum;
        m = mnew;
        o0 *= alpha; o1 *= alpha;

        #pragma unroll
        for (int j = 0; j < 32; j++) {
            float pa = __shfl_sync(0xffffffffu, p0, j);
            float pb = __shfl_sync(0xffffffffu, p1, j);
            o0 = fmaf(pa, Vs[j][lane],           o0);
            o0 = fmaf(pb, Vs[j + 32][lane],      o0);
            o1 = fmaf(pa, Vs[j][lane + 32],      o1);
            o1 = fmaf(pb, Vs[j + 32][lane + 32], o1);
        }
    }
    float inv = 1.f / l;
    float v0 = o0 * inv, v1 = o1 * inv;
    bf16 hh, ll;
    long base = (long)qi * DIM + h * HD;
    split1(v0, hh, ll); ohp[base + lane]      = hh; olp[base + lane]      = ll;
    split1(v1, hh, ll); ohp[base + lane + 32] = hh; olp[base + lane + 32] = ll;
}

// ================= templated bf16x3 mma.sync GEMM, 3-stage, swizzled smem =================
__device__ __forceinline__ void mma_bf16(float* d, const uint32_t* a, const uint32_t* b) {
    asm volatile(
        "mma.sync.aligned.m16n8k16.row.col.f32.bf16.bf16.f32 "
        "{%0,%1,%2,%3}, {%4,%5,%6,%7}, {%8,%9}, {%0,%1,%2,%3};"
        : "+f"(d[0]), "+f"(d[1]), "+f"(d[2]), "+f"(d[3])
        : "r"(a[0]), "r"(a[1]), "r"(a[2]), "r"(a[3]), "r"(b[0]), "r"(b[1]));
}
__device__ __forceinline__ void ldmx4(uint32_t* r, uint32_t addr) {
    asm volatile("ldmatrix.sync.aligned.m8n8.x4.shared.b16 {%0,%1,%2,%3}, [%4];"
                 : "=r"(r[0]), "=r"(r[1]), "=r"(r[2]), "=r"(r[3]) : "r"(addr));
}
__device__ __forceinline__ void cpa16(uint32_t dst, const void* src) {
    asm volatile("cp.async.cg.shared.global [%0], [%1], 16;" :: "r"(dst), "l"(src));
}

template<int BM, int WM, int WN, int THREADS, int MAXB, int K, int EPI>
__global__ __launch_bounds__(THREADS, MAXB)
void gemm_bf3(const bf16* __restrict__ Ah, const bf16* __restrict__ Al,
              const bf16* __restrict__ Bh, const bf16* __restrict__ Bl,
              const float* __restrict__ res, float* __restrict__ C,
              bf16* __restrict__ Eh, bf16* __restrict__ El,
              int N) {
    const int BN = BM;
    const int WARPS_N = BN / WN;
    const int MT = WM / 16;
    const int NT = WN / 8;
    const int PB = BM * 64;
    const int SB = 4 * PB;
    const int KT = K / 32;
    const int CPT = 16 * BM / THREADS;

    extern __shared__ char smc[];
    uint32_t sbase = (uint32_t)__cvta_generic_to_shared(smc);

    int bm = blockIdx.y * BM;
    int bn = blockIdx.x * BN;
    int tid  = threadIdx.x;
    int warp = tid >> 5, lane = tid & 31;
    int wm = (warp / WARPS_N) * WM;
    int wn = (warp % WARPS_N) * WN;
    int g  = lane >> 2, tg = lane & 3;
    int rr = lane & 7, q = lane >> 3;

    int aRowL = wm + rr + 8 * (q & 1);
    int bRowL = wn + rr + 8 * (q >> 1);
    uint32_t aRowOff = (uint32_t)aRowL * 64;
    uint32_t bRowOff = (uint32_t)bRowL * 64;
    uint32_t swA = (uint32_t)((aRowL >> 1) & 3);
    uint32_t swB = (uint32_t)((bRowL >> 1) & 3);
    uint32_t cAk[2], cBk[2];
    #pragma unroll
    for (int ks = 0; ks < 2; ks++) {
        cAk[ks] = ((uint32_t)(2 * ks + (q >> 1)) ^ swA) << 4;
        cBk[ks] = ((uint32_t)(2 * ks + (q & 1))  ^ swB) << 4;
    }

    const bf16* pl[4] = { Ah, Al, Bh, Bl };
    uint32_t dstoff[CPT];
    const bf16* srcb[CPT];
    #pragma unroll
    for (int t = 0; t < CPT; t++) {
        int cid = tid + t * THREADS;
        int p   = cid / (4 * BM);
        int rem = cid - p * (4 * BM);
        int row = rem >> 2, ch = rem & 3;
        dstoff[t] = (uint32_t)p * PB + (uint32_t)row * 64
                  + (((uint32_t)ch ^ (((uint32_t)row >> 1) & 3)) << 4);
        int rowG = ((p < 2) ? bm : bn) + row;
        srcb[t] = pl[p] + (long)rowG * K + ch * 8;
    }

    float acc[MT][NT][4];
    #pragma unroll
    for (int mi = 0; mi < MT; mi++)
        #pragma unroll
        for (int ni = 0; ni < NT; ni++)
            #pragma unroll
            for (int r = 0; r < 4; r++) acc[mi][ni][r] = 0.f;

    auto fill = [&](int s, int k0) {
        uint32_t st = sbase + (uint32_t)s * SB;
        #pragma unroll
        for (int t = 0; t < CPT; t++)
            cpa16(st + dstoff[t], srcb[t] + k0);
        asm volatile("cp.async.commit_group;");
    };

    fill(0, 0);
    fill(1, 32);

    #pragma unroll 3
    for (int kt = 0; kt < KT; kt++) {
        if (kt + 1 < KT) asm volatile("cp.async.wait_group 1;");
        else             asm volatile("cp.async.wait_group 0;");
        __syncthreads();

        if (kt + 2 < KT) fill((kt + 2) % 3, (kt + 2) * 32);

        uint32_t st  = sbase + (uint32_t)(kt % 3) * SB;
        uint32_t pAH = st;
        uint32_t pAL = st + PB;
        uint32_t pBH = st + 2 * PB;
        uint32_t pBL = st + 3 * PB;

        #pragma unroll
        for (int ks = 0; ks < 2; ks++) {
            uint32_t afH[MT][4], bfH[NT][2], bfX[NT][2];
            #pragma unroll
            for (int mi = 0; mi < MT; mi++)
                ldmx4(afH[mi], pAH + aRowOff + (uint32_t)mi * 1024 + cAk[ks]);
            #pragma unroll
            for (int n2 = 0; n2 < NT / 2; n2++) {
                uint32_t t[4];
                ldmx4(t, pBH + bRowOff + (uint32_t)n2 * 1024 + cBk[ks]);
                bfH[2 * n2][0] = t[0]; bfH[2 * n2][1] = t[1];
                bfH[2 * n2 + 1][0] = t[2]; bfH[2 * n2 + 1][1] = t[3];
            }
            #pragma unroll
            for (int mi = 0; mi < MT; mi++)
                #pragma unroll
                for (int ni = 0; ni < NT; ni++)
                    mma_bf16(acc[mi][ni], afH[mi], bfH[ni]);

            #pragma unroll
            for (int n2 = 0; n2 < NT / 2; n2++) {
                uint32_t t[4];
                ldmx4(t, pBL + bRowOff + (uint32_t)n2 * 1024 + cBk[ks]);
                bfX[2 * n2][0] = t[0]; bfX[2 * n2][1] = t[1];
                bfX[2 * n2 + 1][0] = t[2]; bfX[2 * n2 + 1][1] = t[3];
            }
            #pragma unroll
            for (int mi = 0; mi < MT; mi++)
                #pragma unroll
                for (int ni = 0; ni < NT; ni++)
                    mma_bf16(acc[mi][ni], afH[mi], bfX[ni]);

            #pragma unroll
            for (int mi = 0; mi < MT; mi++)
                ldmx4(afH[mi], pAL + aRowOff + (uint32_t)mi * 1024 + cAk[ks]);
            #pragma unroll
            for (int mi = 0; mi < MT; mi++)
                #pragma unroll
                for (int ni = 0; ni < NT; ni++)
                    mma_bf16(acc[mi][ni], afH[mi], bfH[ni]);
        }
    }

    #pragma unroll
    for (int mi = 0; mi < MT; mi++) {
        int row0 = bm + wm + mi * 16 + g;
        #pragma unroll
        for (int ni = 0; ni < NT; ni++) {
            int col = bn + wn + ni * 8 + tg * 2;
            #pragma unroll
            for (int half = 0; half < 2; half++) {
                int row = row0 + half * 8;
                float v0 = acc[mi][ni][half * 2 + 0];
                float v1 = acc[mi][ni][half * 2 + 1];
                if (EPI == 0) {
                    long idx = (long)row * N + col;
                    if (res) { v0 += res[idx]; v1 += res[idx + 1]; }
                    C[idx]     = v0;
                    C[idx + 1] = v1;
                } else {
                    float v = (v0 / (1.f + __expf(-v0))) * v1;
                    bf16 hh, ll; split1(v, hh, ll);
                    long idx = (long)row * (N / 2) + (col >> 1);
                    Eh[idx] = hh;
                    El[idx] = ll;
                }
            }
        }
    }
}

#define GB768      gemm_bf3<128, 64, 32, 256, 2, 768, 0>
#define GB768_SILU gemm_bf3<128, 64, 32, 256, 2, 768, 1>
#define GS768      gemm_bf3< 64, 32, 32, 128, 4, 768, 0>
#define GS2048     gemm_bf3< 64, 32, 32, 128, 4, 2048, 0>
#define SMEM_B  (3 * 4 * 128 * 64)   // 98304
#define SMEM_S  (3 * 4 * 64 * 64)    // 49152

static inline unsigned gblocks(long n, int cap) {
    long b = (n + 255) / 256;
    if (b > cap) b = cap;
    return (unsigned)b;
}

extern "C" void kernel_launch(void* const* d_in, const int* in_sizes, int n_in,
                              void* d_out, int out_size) {
    const int*   tokens   = (const int*)  d_in[0];
    const float* emb      = (const float*)d_in[1];
    const float* wq       = (const float*)d_in[2];
    const float* wk       = (const float*)d_in[3];
    const float* wv       = (const float*)d_in[4];
    const float* wo       = (const float*)d_in[5];
    const float* w1       = (const float*)d_in[6];
    const float* w2       = (const float*)d_in[7];
    const float* w3       = (const float*)d_in[8];
    const float* attn_nw  = (const float*)d_in[9];
    const float* ffn_nw   = (const float*)d_in[10];
    const float* norm_w   = (const float*)d_in[11];
    const float* out_w    = (const float*)d_in[12];
    float* out = (float*)d_out;

    float *h, *qkv;
    cudaGetSymbolAddress((void**)&h,   g_h);
    cudaGetSymbolAddress((void**)&qkv, g_qkv);

    bf16 *wqkvh, *wqkvl, *woh, *wol, *w13h, *w13l, *w2h, *w2l, *owh, *owl;
    bf16 *xh, *xl, *oh, *ol, *h1h, *h1l;
    cudaGetSymbolAddress((void**)&wqkvh, g_wqkv_h); cudaGetSymbolAddress((void**)&wqkvl, g_wqkv_l);
    cudaGetSymbolAddress((void**)&woh,   g_wo_h);   cudaGetSymbolAddress((void**)&wol,   g_wo_l);
    cudaGetSymbolAddress((void**)&w13h,  g_w13_h);  cudaGetSymbolAddress((void**)&w13l,  g_w13_l);
    cudaGetSymbolAddress((void**)&w2h,   g_w2_h);   cudaGetSymbolAddress((void**)&w2l,   g_w2_l);
    cudaGetSymbolAddress((void**)&owh,   g_ow_h);   cudaGetSymbolAddress((void**)&owl,   g_ow_l);
    cudaGetSymbolAddress((void**)&xh,  g_xh);  cudaGetSymbolAddress((void**)&xl,  g_xl);
    cudaGetSymbolAddress((void**)&oh,  g_oh);  cudaGetSymbolAddress((void**)&ol,  g_ol);
    cudaGetSymbolAddress((void**)&h1h, g_h1h); cudaGetSymbolAddress((void**)&h1l, g_h1l);

    cudaFuncSetAttribute(GB768,      cudaFuncAttributeMaxDynamicSharedMemorySize, SMEM_B);
    cudaFuncSetAttribute(GB768_SILU, cudaFuncAttributeMaxDynamicSharedMemorySize, SMEM_B);
    cudaFuncSetAttribute(GS768,      cudaFuncAttributeMaxDynamicSharedMemorySize, SMEM_S);
    cudaFuncSetAttribute(GS2048,     cudaFuncAttributeMaxDynamicSharedMemorySize, SMEM_S);

    // ---- weight conversion: 5 big launches ----
    split_qkv_all<<<gblocks((long)NL * 3 * DIM * DIM / 4, 16384), 256>>>(
        (const float4*)wq, (const float4*)wk, (const float4*)wv,
        (bf162*)wqkvh, (bf162*)wqkvl);
    split4_kernel<<<gblocks((long)NL * DIM * DIM / 4, 16384), 256>>>(
        (const float4*)wo, (bf162*)woh, (bf162*)wol, (long)NL * DIM * DIM / 4);
    split_w13_all<<<gblocks((long)NL * N13 * DIM / 4, 16384), 256>>>(
        w1, w3, (bf162*)w13h, (bf162*)w13l);
    split2_pad_kernel<<<gblocks((long)NL * DIM * HIDP / 2, 16384), 256>>>(
        w2, (bf162*)w2h, (bf162*)w2l, NL * DIM, HIDDEN, HIDP);
    split4_kernel<<<gblocks((long)VOCAB * DIM / 4, 16384), 256>>>(
        (const float4*)out_w, (bf162*)owh, (bf162*)owl, (long)VOCAB * DIM / 4);

    // ---- forward ----
    embed_kernel<<<(SEQ * DIM + 255) / 256, 256>>>(tokens, emb, h);

    for (int L = 0; L < NL; L++) {
        rmsnorm_split_kernel<<<SEQ, 256>>>(h, attn_nw + L * DIM, xh, xl);

        GB768<<<dim3(QKVN / 128, SEQ / 128), 256, SMEM_B>>>(
            xh, xl, wqkvh + (long)L * QKVN * DIM, wqkvl + (long)L * QKVN * DIM,
            nullptr, qkv, nullptr, nullptr, QKVN);

        rope_kernel<<<(SEQ * NH * (HD / 2) + 255) / 256, 256>>>(qkv);
        attn_kernel<<<dim3(SEQ / BQ, NH), 32 * BQ>>>(qkv, oh, ol);

        GS768<<<dim3(DIM / 64, SEQ / 64), 128, SMEM_S>>>(
            oh, ol, woh + (long)L * DIM * DIM, wol + (long)L * DIM * DIM,
            h, h, nullptr, nullptr, DIM);

        rmsnorm_split_kernel<<<SEQ, 256>>>(h, ffn_nw + L * DIM, xh, xl);

        GB768_SILU<<<dim3(N13 / 128, SEQ / 128), 256, SMEM_B>>>(
            xh, xl, w13h + (long)L * N13 * DIM, w13l + (long)L * N13 * DIM,
            nullptr, nullptr, h1h, h1l, N13);

        GS2048<<<dim3(DIM / 64, SEQ / 64), 128, SMEM_S>>>(
            h1h, h1l, w2h + (long)L * DIM * HIDP, w2l + (long)L * DIM * HIDP,
            h, h, nullptr, nullptr, DIM);
    }

    rmsnorm_split_kernel<<<SEQ, 256>>>(h, norm_w, xh, xl);

    GB768<<<dim3(VOCAB / 128, SEQ / 128), 256, SMEM_B>>>(
        xh, xl, owh, owl, nullptr, out, nullptr, nullptr, VOCAB);
}

// round 15
// speedup vs baseline: 1.0367x; 1.0342x over previous
#include <cuda_runtime.h>
#include <cuda_bf16.h>
#include <math.h>
#include <stdint.h>

#define SEQ     2048
#define DIM     768
#define NH      12
#define HD      64
#define HIDDEN  2042
#define HIDP    2048
#define N13     4096
#define QKVN    2304
#define VOCAB   32000
#define NL      4
#define THETA   10000.0f
#define ATT_SCALE 0.125f

typedef __nv_bfloat16 bf16;
typedef __nv_bfloat162 bf162;

// ---------------- fp32 scratch ----------------
__device__ float g_h  [SEQ * DIM];
__device__ float g_qkv[SEQ * QKVN];

// ---------------- bf16 hi/lo planes (16B aligned) ----------------
__device__ __align__(16) bf16 g_wqkv_h[NL * QKVN * DIM],  g_wqkv_l[NL * QKVN * DIM];
__device__ __align__(16) bf16 g_wo_h  [NL * DIM * DIM],   g_wo_l  [NL * DIM * DIM];
__device__ __align__(16) bf16 g_w13_h [NL * N13 * DIM],   g_w13_l [NL * N13 * DIM];  // interleaved w1/w3
__device__ __align__(16) bf16 g_w2_h  [NL * DIM * HIDP],  g_w2_l  [NL * DIM * HIDP];
__device__ __align__(16) bf16 g_ow_h  [VOCAB * DIM],      g_ow_l  [VOCAB * DIM];
__device__ __align__(16) bf16 g_xh [SEQ * DIM],  g_xl [SEQ * DIM];
__device__ __align__(16) bf16 g_oh [SEQ * DIM],  g_ol [SEQ * DIM];
__device__ __align__(16) bf16 g_h1h[SEQ * HIDP], g_h1l[SEQ * HIDP];

// ---------------- helpers ----------------
__device__ __forceinline__ void split1(float v, bf16& h, bf16& l) {
    h = __float2bfloat16(v);
    l = __float2bfloat16(v - __bfloat162float(h));
}

__device__ __forceinline__ void store_split4(bf162* dh, bf162* dl, long d2, float4 v) {
    bf16 h0, l0, h1, l1, h2, l2, h3, l3;
    split1(v.x, h0, l0); split1(v.y, h1, l1);
    split1(v.z, h2, l2); split1(v.w, h3, l3);
    dh[d2]     = __halves2bfloat162(h0, h1);
    dh[d2 + 1] = __halves2bfloat162(h2, h3);
    dl[d2]     = __halves2bfloat162(l0, l1);
    dl[d2 + 1] = __halves2bfloat162(l2, l3);
}

__global__ void split4_kernel(const float4* __restrict__ src,
                              bf162* __restrict__ dh, bf162* __restrict__ dl,
                              long n4) {
    long stride = (long)gridDim.x * blockDim.x;
    for (long i = (long)blockIdx.x * blockDim.x + threadIdx.x; i < n4; i += stride)
        store_split4(dh, dl, i * 2, src[i]);
}

__global__ void split_qkv_all(const float4* __restrict__ wq, const float4* __restrict__ wk,
                              const float4* __restrict__ wv,
                              bf162* __restrict__ dh, bf162* __restrict__ dl) {
    const long SEG4 = (long)DIM * DIM / 4;
    long n4 = NL * 3 * SEG4;
    long stride = (long)gridDim.x * blockDim.x;
    for (long i = (long)blockIdx.x * blockDim.x + threadIdx.x; i < n4; i += stride) {
        long seg = i / SEG4;
        int L = (int)(seg / 3), t = (int)(seg % 3);
        long o4 = i - seg * SEG4;
        const float4* src = (t == 0 ? wq : t == 1 ? wk : wv) + L * SEG4 + o4;
        long d4 = ((long)L * QKVN + t * DIM) * (DIM / 4) + o4;
        store_split4(dh, dl, d4 * 2, *src);
    }
}

__global__ void split_w13_all(const float* __restrict__ w1, const float* __restrict__ w3,
                              bf162* __restrict__ dh, bf162* __restrict__ dl) {
    const int D4 = DIM / 4;
    long n4 = (long)NL * N13 * D4;
    long stride = (long)gridDim.x * blockDim.x;
    for (long i = (long)blockIdx.x * blockDim.x + threadIdx.x; i < n4; i += stride) {
        int col4 = (int)(i % D4);
        long rr = i / D4;
        int r = (int)(rr % N13);
        int L = (int)(rr / N13);
        int j = r >> 1, t = r & 1;
        float4 v = make_float4(0.f, 0.f, 0.f, 0.f);
        if (j < HIDDEN) {
            const float* s = (t ? w3 : w1) + ((long)L * HIDDEN + j) * DIM + col4 * 4;
            v = *(const float4*)s;
        }
        store_split4(dh, dl, i * 2, v);
    }
}

__global__ void split2_pad_kernel(const float* __restrict__ src,
                                  bf162* __restrict__ dh, bf162* __restrict__ dl,
                                  int rows, int Ks, int Kd) {
    long n2 = (long)rows * (Kd / 2);
    long stride = (long)gridDim.x * blockDim.x;
    for (long i = (long)blockIdx.x * blockDim.x + threadIdx.x; i < n2; i += stride) {
        int r  = (int)(i / (Kd / 2));
        int c2 = (int)(i - (long)r * (Kd / 2));
        float2 v = make_float2(0.f, 0.f);
        if (c2 * 2 + 1 < Ks)
            v = *reinterpret_cast<const float2*>(src + (long)r * Ks + c2 * 2);
        bf16 h0, l0, h1, l1;
        split1(v.x, h0, l0); split1(v.y, h1, l1);
        dh[i] = __halves2bfloat162(h0, h1);
        dl[i] = __halves2bfloat162(l0, l1);
    }
}

__global__ void embed_kernel(const int* __restrict__ tokens,
                             const float* __restrict__ emb,
                             float* __restrict__ h) {
    int i = blockIdx.x * blockDim.x + threadIdx.x;
    if (i < SEQ * DIM) {
        int s = i / DIM, d = i - s * DIM;
        h[i] = emb[(long)tokens[s] * DIM + d];
    }
}

__global__ void rmsnorm_split_kernel(const float* __restrict__ x,
                                     const float* __restrict__ w,
                                     bf16* __restrict__ yh, bf16* __restrict__ yl) {
    int row = blockIdx.x;
    const float2* xr = (const float2*)(x + (long)row * DIM);
    const float2* w2p = (const float2*)w;
    float ss = 0.f;
    #pragma unroll
    for (int d = threadIdx.x; d < DIM / 2; d += 256) {
        float2 t = xr[d];
        ss += t.x * t.x + t.y * t.y;
    }
    #pragma unroll
    for (int off = 16; off; off >>= 1) ss += __shfl_xor_sync(0xffffffffu, ss, off);
    __shared__ float sred[8];
    if ((threadIdx.x & 31) == 0) sred[threadIdx.x >> 5] = ss;
    __syncthreads();
    __shared__ float s_inv;
    if (threadIdx.x == 0) {
        float tot = 0.f;
        #pragma unroll
        for (int i = 0; i < 8; i++) tot += sred[i];
        s_inv = rsqrtf(tot / (float)DIM + 1e-6f);
    }
    __syncthreads();
    float inv = s_inv;
    bf162* yh2 = (bf162*)(yh + (long)row * DIM);
    bf162* yl2 = (bf162*)(yl + (long)row * DIM);
    for (int d = threadIdx.x; d < DIM / 2; d += 256) {
        float2 t = xr[d], ww = w2p[d];
        float v0 = t.x * inv * ww.x, v1 = t.y * inv * ww.y;
        bf16 h0, l0, h1, l1;
        split1(v0, h0, l0); split1(v1, h1, l1);
        yh2[d] = __halves2bfloat162(h0, h1);
        yl2[d] = __halves2bfloat162(l0, l1);
    }
}

__global__ void rope_kernel(float* __restrict__ qkv) {
    int i = blockIdx.x * blockDim.x + threadIdx.x;
    if (i >= SEQ * NH * (HD / 2)) return;
    int p  = i % (HD / 2);
    int sh = i / (HD / 2);
    int h  = sh % NH;
    int s  = sh / NH;
    float freq = powf(THETA, -(2.0f * (float)p) / (float)HD);
    float ang  = (float)s * freq;
    float c = cosf(ang), sn = sinf(ang);
    long base = (long)s * QKVN + h * HD + 2 * p;
    float a = qkv[base], b = qkv[base + 1];
    qkv[base]     = a * c - b * sn;
    qkv[base + 1] = a * sn + b * c;
    a = qkv[base + DIM]; b = qkv[base + DIM + 1];
    qkv[base + DIM]     = a * c - b * sn;
    qkv[base + DIM + 1] = a * sn + b * c;
}

// ---------------- flash attention: R12 body + double-buffered K/V (4B cp.async) ----------------
#define BQ 16
#define ATT_TILE (64 * 65)                  // floats per K or V tile (stride 65)
#define ATT_SMEM ((4 * ATT_TILE + BQ * HD) * 4)   // 2 bufs x (K+V) + Q : 70,656 B

__device__ __forceinline__ void cpa4(uint32_t dst, const void* src) {
    asm volatile("cp.async.ca.shared.global [%0], [%1], 4;" :: "r"(dst), "l"(src));
}

__global__ __launch_bounds__(32 * BQ)
void attn_kernel(const float* __restrict__ qkv,
                 bf16* __restrict__ ohp, bf16* __restrict__ olp) {
    extern __shared__ float sm_att[];
    float* KsBuf = sm_att;                       // [2][64][65]
    float* VsBuf = sm_att + 2 * ATT_TILE;        // [2][64][65]
    float* Qs    = sm_att + 4 * ATT_TILE;        // [BQ][HD]

    int h    = blockIdx.y;
    int q0   = blockIdx.x * BQ;
    int warp = threadIdx.x >> 5;
    int lane = threadIdx.x & 31;
    int qi   = q0 + warp;

    uint32_t sK = (uint32_t)__cvta_generic_to_shared(KsBuf);
    uint32_t sV = (uint32_t)__cvta_generic_to_shared(VsBuf);

    Qs[warp * HD + lane]      = qkv[(long)qi * QKVN + h * HD + lane];
    Qs[warp * HD + lane + 32] = qkv[(long)qi * QKVN + h * HD + lane + 32];

    float m = -INFINITY, l = 0.f, o0 = 0.f, o1 = 0.f;
    int kend   = q0 + BQ;
    int ntiles = (kend + 63) >> 6;

    // loader: 8 K elems + 8 V elems per thread per tile (64*64 each / 512 thr)
    auto fill = [&](int s, int t0) {
        uint32_t bK = sK + (uint32_t)s * ATT_TILE * 4;
        uint32_t bV = sV + (uint32_t)s * ATT_TILE * 4;
        #pragma unroll
        for (int i = 0; i < 8; i++) {
            int idx = threadIdx.x + i * 512;          // 0..4095
            int kj = idx >> 6, d = idx & 63;
            long row = (long)(t0 + kj) * QKVN + h * HD + d;
            uint32_t so = (uint32_t)(kj * 65 + d) * 4;
            cpa4(bK + so, qkv + row + DIM);
            cpa4(bV + so, qkv + row + 2 * DIM);
        }
        asm volatile("cp.async.commit_group;");
    };

    fill(0, 0);

    for (int tt = 0; tt < ntiles; tt++) {
        asm volatile("cp.async.wait_group 0;");
        __syncthreads();
        if (tt + 1 < ntiles) fill((tt + 1) & 1, (tt + 1) << 6);

        int t0 = tt << 6;
        const float* Ks = KsBuf + (tt & 1) * ATT_TILE;
        const float* Vs = VsBuf + (tt & 1) * ATT_TILE;

        float s0 = 0.f, s1 = 0.f;
        #pragma unroll
        for (int d = 0; d < HD; d++) {
            float qd = Qs[warp * HD + d];
            s0 = fmaf(qd, Ks[lane * 65 + d],        s0);
            s1 = fmaf(qd, Ks[(lane + 32) * 65 + d], s1);
        }
        s0 *= ATT_SCALE; s1 *= ATT_SCALE;
        if (t0 + lane      > qi) s0 = -INFINITY;
        if (t0 + lane + 32 > qi) s1 = -INFINITY;

        float mt = fmaxf(s0, s1);
        #pragma unroll
        for (int off = 16; off; off >>= 1)
            mt = fmaxf(mt, __shfl_xor_sync(0xffffffffu, mt, off));
        float mnew  = fmaxf(m, mt);
        float alpha = __expf(m - mnew);
        float p0 = __expf(s0 - mnew);
        float p1 = __expf(s1 - mnew);
        float lsum = p0 + p1;
        #pragma unroll
        for (int off = 16; off; off >>= 1)
            lsum += __shfl_xor_sync(0xffffffffu, lsum, off);
        l = l * alpha + lsum;
        m = mnew;
        o0 *= alpha; o1 *= alpha;

        #pragma unroll
        for (int j = 0; j < 32; j++) {
            float pa = __shfl_sync(0xffffffffu, p0, j);
            float pb = __shfl_sync(0xffffffffu, p1, j);
            o0 = fmaf(pa, Vs[j * 65 + lane],             o0);
            o0 = fmaf(pb, Vs[(j + 32) * 65 + lane],      o0);
            o1 = fmaf(pa, Vs[j * 65 + lane + 32],        o1);
            o1 = fmaf(pb, Vs[(j + 32) * 65 + lane + 32], o1);
        }
    }
    float inv = 1.f / l;
    float v0 = o0 * inv, v1 = o1 * inv;
    bf16 hh, ll;
    long base = (long)qi * DIM + h * HD;
    split1(v0, hh, ll); ohp[base + lane]      = hh; olp[base + lane]      = ll;
    split1(v1, hh, ll); ohp[base + lane + 32] = hh; olp[base + lane + 32] = ll;
}

// ================= templated bf16x3 mma.sync GEMM, 3-stage, swizzled smem =================
__device__ __forceinline__ void mma_bf16(float* d, const uint32_t* a, const uint32_t* b) {
    asm volatile(
        "mma.sync.aligned.m16n8k16.row.col.f32.bf16.bf16.f32 "
        "{%0,%1,%2,%3}, {%4,%5,%6,%7}, {%8,%9}, {%0,%1,%2,%3};"
        : "+f"(d[0]), "+f"(d[1]), "+f"(d[2]), "+f"(d[3])
        : "r"(a[0]), "r"(a[1]), "r"(a[2]), "r"(a[3]), "r"(b[0]), "r"(b[1]));
}
__device__ __forceinline__ void ldmx4(uint32_t* r, uint32_t addr) {
    asm volatile("ldmatrix.sync.aligned.m8n8.x4.shared.b16 {%0,%1,%2,%3}, [%4];"
                 : "=r"(r[0]), "=r"(r[1]), "=r"(r[2]), "=r"(r[3]) : "r"(addr));
}
__device__ __forceinline__ void cpa16(uint32_t dst, const void* src) {
    asm volatile("cp.async.cg.shared.global [%0], [%1], 16;" :: "r"(dst), "l"(src));
}

template<int BM, int WM, int WN, int THREADS, int MAXB, int K, int EPI>
__global__ __launch_bounds__(THREADS, MAXB)
void gemm_bf3(const bf16* __restrict__ Ah, const bf16* __restrict__ Al,
              const bf16* __restrict__ Bh, const bf16* __restrict__ Bl,
              const float* __restrict__ res, float* __restrict__ C,
              bf16* __restrict__ Eh, bf16* __restrict__ El,
              int N) {
    const int BN = BM;
    const int WARPS_N = BN / WN;
    const int MT = WM / 16;
    const int NT = WN / 8;
    const int PB = BM * 64;
    const int SB = 4 * PB;
    const int KT = K / 32;
    const int CPT = 16 * BM / THREADS;

    extern __shared__ char smc[];
    uint32_t sbase = (uint32_t)__cvta_generic_to_shared(smc);

    int bm = blockIdx.y * BM;
    int bn = blockIdx.x * BN;
    int tid  = threadIdx.x;
    int warp = tid >> 5, lane = tid & 31;
    int wm = (warp / WARPS_N) * WM;
    int wn = (warp % WARPS_N) * WN;
    int g  = lane >> 2, tg = lane & 3;
    int rr = lane & 7, q = lane >> 3;

    int aRowL = wm + rr + 8 * (q & 1);
    int bRowL = wn + rr + 8 * (q >> 1);
    uint32_t aRowOff = (uint32_t)aRowL * 64;
    uint32_t bRowOff = (uint32_t)bRowL * 64;
    uint32_t swA = (uint32_t)((aRowL >> 1) & 3);
    uint32_t swB = (uint32_t)((bRowL >> 1) & 3);
    uint32_t cAk[2], cBk[2];
    #pragma unroll
    for (int ks = 0; ks < 2; ks++) {
        cAk[ks] = ((uint32_t)(2 * ks + (q >> 1)) ^ swA) << 4;
        cBk[ks] = ((uint32_t)(2 * ks + (q & 1))  ^ swB) << 4;
    }

    const bf16* pl[4] = { Ah, Al, Bh, Bl };
    uint32_t dstoff[CPT];
    const bf16* srcb[CPT];
    #pragma unroll
    for (int t = 0; t < CPT; t++) {
        int cid = tid + t * THREADS;
        int p   = cid / (4 * BM);
        int rem = cid - p * (4 * BM);
        int row = rem >> 2, ch = rem & 3;
        dstoff[t] = (uint32_t)p * PB + (uint32_t)row * 64
                  + (((uint32_t)ch ^ (((uint32_t)row >> 1) & 3)) << 4);
        int rowG = ((p < 2) ? bm : bn) + row;
        srcb[t] = pl[p] + (long)rowG * K + ch * 8;
    }

    float acc[MT][NT][4];
    #pragma unroll
    for (int mi = 0; mi < MT; mi++)
        #pragma unroll
        for (int ni = 0; ni < NT; ni++)
            #pragma unroll
            for (int r = 0; r < 4; r++) acc[mi][ni][r] = 0.f;

    auto fill = [&](int s, int k0) {
        uint32_t st = sbase + (uint32_t)s * SB;
        #pragma unroll
        for (int t = 0; t < CPT; t++)
            cpa16(st + dstoff[t], srcb[t] + k0);
        asm volatile("cp.async.commit_group;");
    };

    fill(0, 0);
    fill(1, 32);

    #pragma unroll 3
    for (int kt = 0; kt < KT; kt++) {
        if (kt + 1 < KT) asm volatile("cp.async.wait_group 1;");
        else             asm volatile("cp.async.wait_group 0;");
        __syncthreads();

        if (kt + 2 < KT) fill((kt + 2) % 3, (kt + 2) * 32);

        uint32_t st  = sbase + (uint32_t)(kt % 3) * SB;
        uint32_t pAH = st;
        uint32_t pAL = st + PB;
        uint32_t pBH = st + 2 * PB;
        uint32_t pBL = st + 3 * PB;

        #pragma unroll
        for (int ks = 0; ks < 2; ks++) {
            uint32_t afH[MT][4], bfH[NT][2], bfX[NT][2];
            #pragma unroll
            for (int mi = 0; mi < MT; mi++)
                ldmx4(afH[mi], pAH + aRowOff + (uint32_t)mi * 1024 + cAk[ks]);
            #pragma unroll
            for (int n2 = 0; n2 < NT / 2; n2++) {
                uint32_t t[4];
                ldmx4(t, pBH + bRowOff + (uint32_t)n2 * 1024 + cBk[ks]);
                bfH[2 * n2][0] = t[0]; bfH[2 * n2][1] = t[1];
                bfH[2 * n2 + 1][0] = t[2]; bfH[2 * n2 + 1][1] = t[3];
            }
            #pragma unroll
            for (int mi = 0; mi < MT; mi++)
                #pragma unroll
                for (int ni = 0; ni < NT; ni++)
                    mma_bf16(acc[mi][ni], afH[mi], bfH[ni]);

            #pragma unroll
            for (int n2 = 0; n2 < NT / 2; n2++) {
                uint32_t t[4];
                ldmx4(t, pBL + bRowOff + (uint32_t)n2 * 1024 + cBk[ks]);
                bfX[2 * n2][0] = t[0]; bfX[2 * n2][1] = t[1];
                bfX[2 * n2 + 1][0] = t[2]; bfX[2 * n2 + 1][1] = t[3];
            }
            #pragma unroll
            for (int mi = 0; mi < MT; mi++)
                #pragma unroll
                for (int ni = 0; ni < NT; ni++)
                    mma_bf16(acc[mi][ni], afH[mi], bfX[ni]);

            #pragma unroll
            for (int mi = 0; mi < MT; mi++)
                ldmx4(afH[mi], pAL + aRowOff + (uint32_t)mi * 1024 + cAk[ks]);
            #pragma unroll
            for (int mi = 0; mi < MT; mi++)
                #pragma unroll
                for (int ni = 0; ni < NT; ni++)
                    mma_bf16(acc[mi][ni], afH[mi], bfH[ni]);
        }
    }

    #pragma unroll
    for (int mi = 0; mi < MT; mi++) {
        int row0 = bm + wm + mi * 16 + g;
        #pragma unroll
        for (int ni = 0; ni < NT; ni++) {
            int col = bn + wn + ni * 8 + tg * 2;
            #pragma unroll
            for (int half = 0; half < 2; half++) {
                int row = row0 + half * 8;
                float v0 = acc[mi][ni][half * 2 + 0];
                float v1 = acc[mi][ni][half * 2 + 1];
                if (EPI == 0) {
                    long idx = (long)row * N + col;
                    if (res) { v0 += res[idx]; v1 += res[idx + 1]; }
                    C[idx]     = v0;
                    C[idx + 1] = v1;
                } else {
                    float v = (v0 / (1.f + __expf(-v0))) * v1;
                    bf16 hh, ll; split1(v, hh, ll);
                    long idx = (long)row * (N / 2) + (col >> 1);
                    Eh[idx] = hh;
                    El[idx] = ll;
                }
            }
        }
    }
}

#define GB768      gemm_bf3<128, 64, 32, 256, 2, 768, 0>
#define GB768_SILU gemm_bf3<128, 64, 32, 256, 2, 768, 1>
#define GS768      gemm_bf3< 64, 32, 32, 128, 4, 768, 0>
#define GS2048     gemm_bf3< 64, 32, 32, 128, 4, 2048, 0>
#define SMEM_B  (3 * 4 * 128 * 64)   // 98304
#define SMEM_S  (3 * 4 * 64 * 64)    // 49152

static inline unsigned gblocks(long n, int cap) {
    long b = (n + 255) / 256;
    if (b > cap) b = cap;
    return (unsigned)b;
}

extern "C" void kernel_launch(void* const* d_in, const int* in_sizes, int n_in,
                              void* d_out, int out_size) {
    const int*   tokens   = (const int*)  d_in[0];
    const float* emb      = (const float*)d_in[1];
    const float* wq       = (const float*)d_in[2];
    const float* wk       = (const float*)d_in[3];
    const float* wv       = (const float*)d_in[4];
    const float* wo       = (const float*)d_in[5];
    const float* w1       = (const float*)d_in[6];
    const float* w2       = (const float*)d_in[7];
    const float* w3       = (const float*)d_in[8];
    const float* attn_nw  = (const float*)d_in[9];
    const float* ffn_nw   = (const float*)d_in[10];
    const float* norm_w   = (const float*)d_in[11];
    const float* out_w    = (const float*)d_in[12];
    float* out = (float*)d_out;

    float *h, *qkv;
    cudaGetSymbolAddress((void**)&h,   g_h);
    cudaGetSymbolAddress((void**)&qkv, g_qkv);

    bf16 *wqkvh, *wqkvl, *woh, *wol, *w13h, *w13l, *w2h, *w2l, *owh, *owl;
    bf16 *xh, *xl, *oh, *ol, *h1h, *h1l;
    cudaGetSymbolAddress((void**)&wqkvh, g_wqkv_h); cudaGetSymbolAddress((void**)&wqkvl, g_wqkv_l);
    cudaGetSymbolAddress((void**)&woh,   g_wo_h);   cudaGetSymbolAddress((void**)&wol,   g_wo_l);
    cudaGetSymbolAddress((void**)&w13h,  g_w13_h);  cudaGetSymbolAddress((void**)&w13l,  g_w13_l);
    cudaGetSymbolAddress((void**)&w2h,   g_w2_h);   cudaGetSymbolAddress((void**)&w2l,   g_w2_l);
    cudaGetSymbolAddress((void**)&owh,   g_ow_h);   cudaGetSymbolAddress((void**)&owl,   g_ow_l);
    cudaGetSymbolAddress((void**)&xh,  g_xh);  cudaGetSymbolAddress((void**)&xl,  g_xl);
    cudaGetSymbolAddress((void**)&oh,  g_oh);  cudaGetSymbolAddress((void**)&ol,  g_ol);
    cudaGetSymbolAddress((void**)&h1h, g_h1h); cudaGetSymbolAddress((void**)&h1l, g_h1l);

    cudaFuncSetAttribute(GB768,      cudaFuncAttributeMaxDynamicSharedMemorySize, SMEM_B);
    cudaFuncSetAttribute(GB768_SILU, cudaFuncAttributeMaxDynamicSharedMemorySize, SMEM_B);
    cudaFuncSetAttribute(GS768,      cudaFuncAttributeMaxDynamicSharedMemorySize, SMEM_S);
    cudaFuncSetAttribute(GS2048,     cudaFuncAttributeMaxDynamicSharedMemorySize, SMEM_S);
    cudaFuncSetAttribute(attn_kernel, cudaFuncAttributeMaxDynamicSharedMemorySize, ATT_SMEM);

    // ---- weight conversion: 5 big launches ----
    split_qkv_all<<<gblocks((long)NL * 3 * DIM * DIM / 4, 16384), 256>>>(
        (const float4*)wq, (const float4*)wk, (const float4*)wv,
        (bf162*)wqkvh, (bf162*)wqkvl);
    split4_kernel<<<gblocks((long)NL * DIM * DIM / 4, 16384), 256>>>(
        (const float4*)wo, (bf162*)woh, (bf162*)wol, (long)NL * DIM * DIM / 4);
    split_w13_all<<<gblocks((long)NL * N13 * DIM / 4, 16384), 256>>>(
        w1, w3, (bf162*)w13h, (bf162*)w13l);
    split2_pad_kernel<<<gblocks((long)NL * DIM * HIDP / 2, 16384), 256>>>(
        w2, (bf162*)w2h, (bf162*)w2l, NL * DIM, HIDDEN, HIDP);
    split4_kernel<<<gblocks((long)VOCAB * DIM / 4, 16384), 256>>>(
        (const float4*)out_w, (bf162*)owh, (bf162*)owl, (long)VOCAB * DIM / 4);

    // ---- forward ----
    embed_kernel<<<(SEQ * DIM + 255) / 256, 256>>>(tokens, emb, h);

    for (int L = 0; L < NL; L++) {
        rmsnorm_split_kernel<<<SEQ, 256>>>(h, attn_nw + L * DIM, xh, xl);

        GB768<<<dim3(QKVN / 128, SEQ / 128), 256, SMEM_B>>>(
            xh, xl, wqkvh + (long)L * QKVN * DIM, wqkvl + (long)L * QKVN * DIM,
            nullptr, qkv, nullptr, nullptr, QKVN);

        rope_kernel<<<(SEQ * NH * (HD / 2) + 255) / 256, 256>>>(qkv);
        attn_kernel<<<dim3(SEQ / BQ, NH), 32 * BQ, ATT_SMEM>>>(qkv, oh, ol);

        GS768<<<dim3(DIM / 64, SEQ / 64), 128, SMEM_S>>>(
            oh, ol, woh + (long)L * DIM * DIM, wol + (long)L * DIM * DIM,
            h, h, nullptr, nullptr, DIM);

        rmsnorm_split_kernel<<<SEQ, 256>>>(h, ffn_nw + L * DIM, xh, xl);

        GB768_SILU<<<dim3(N13 / 128, SEQ / 128), 256, SMEM_B>>>(
            xh, xl, w13h + (long)L * N13 * DIM, w13l + (long)L * N13 * DIM,
            nullptr, nullptr, h1h, h1l, N13);

        GS2048<<<dim3(DIM / 64, SEQ / 64), 128, SMEM_S>>>(
            h1h, h1l, w2h + (long)L * DIM * HIDP, w2l + (long)L * DIM * HIDP,
            h, h, nullptr, nullptr, DIM);
    }

    rmsnorm_split_kernel<<<SEQ, 256>>>(h, norm_w, xh, xl);

    GB768<<<dim3(VOCAB / 128, SEQ / 128), 256, SMEM_B>>>(
        xh, xl, owh, owl, nullptr, out, nullptr, nullptr, VOCAB);
}

// round 16
// speedup vs baseline: 1.0443x; 1.0073x over previous
#include <cuda_runtime.h>
#include <cuda_bf16.h>
#include <math.h>
#include <stdint.h>

#define SEQ     2048
#define DIM     768
#define NH      12
#define HD      64
#define HIDDEN  2042
#define HIDP    2048
#define N13     4096
#define QKVN    2304
#define VOCAB   32000
#define NL      4
#define THETA   10000.0f
#define ATT_SCALE 0.125f

typedef __nv_bfloat16 bf16;
typedef __nv_bfloat162 bf162;

// ---------------- fp32 scratch ----------------
__device__ float g_h  [SEQ * DIM];
__device__ float g_qkv[SEQ * QKVN];
__device__ float2 g_rope[SEQ * (HD / 2)];   // cos/sin per (pos, pair)

// ---------------- bf16 hi/lo planes (16B aligned) ----------------
__device__ __align__(16) bf16 g_wqkv_h[NL * QKVN * DIM],  g_wqkv_l[NL * QKVN * DIM];
__device__ __align__(16) bf16 g_wo_h  [NL * DIM * DIM],   g_wo_l  [NL * DIM * DIM];
__device__ __align__(16) bf16 g_w13_h [NL * N13 * DIM],   g_w13_l [NL * N13 * DIM];  // interleaved w1/w3
__device__ __align__(16) bf16 g_w2_h  [NL * DIM * HIDP],  g_w2_l  [NL * DIM * HIDP];
__device__ __align__(16) bf16 g_ow_h  [VOCAB * DIM],      g_ow_l  [VOCAB * DIM];
__device__ __align__(16) bf16 g_xh [SEQ * DIM],  g_xl [SEQ * DIM];
__device__ __align__(16) bf16 g_oh [SEQ * DIM],  g_ol [SEQ * DIM];
__device__ __align__(16) bf16 g_h1h[SEQ * HIDP], g_h1l[SEQ * HIDP];

// ---------------- helpers ----------------
__device__ __forceinline__ void split1(float v, bf16& h, bf16& l) {
    h = __float2bfloat16(v);
    l = __float2bfloat16(v - __bfloat162float(h));
}

__device__ __forceinline__ void store_split4(bf162* dh, bf162* dl, long d2, float4 v) {
    bf16 h0, l0, h1, l1, h2, l2, h3, l3;
    split1(v.x, h0, l0); split1(v.y, h1, l1);
    split1(v.z, h2, l2); split1(v.w, h3, l3);
    dh[d2]     = __halves2bfloat162(h0, h1);
    dh[d2 + 1] = __halves2bfloat162(h2, h3);
    dl[d2]     = __halves2bfloat162(l0, l1);
    dl[d2 + 1] = __halves2bfloat162(l2, l3);
}

__global__ void split4_kernel(const float4* __restrict__ src,
                              bf162* __restrict__ dh, bf162* __restrict__ dl,
                              long n4) {
    long stride = (long)gridDim.x * blockDim.x;
    for (long i = (long)blockIdx.x * blockDim.x + threadIdx.x; i < n4; i += stride)
        store_split4(dh, dl, i * 2, src[i]);
}

__global__ void split_qkv_all(const float4* __restrict__ wq, const float4* __restrict__ wk,
                              const float4* __restrict__ wv,
                              bf162* __restrict__ dh, bf162* __restrict__ dl) {
    const long SEG4 = (long)DIM * DIM / 4;
    long n4 = NL * 3 * SEG4;
    long stride = (long)gridDim.x * blockDim.x;
    for (long i = (long)blockIdx.x * blockDim.x + threadIdx.x; i < n4; i += stride) {
        long seg = i / SEG4;
        int L = (int)(seg / 3), t = (int)(seg % 3);
        long o4 = i - seg * SEG4;
        const float4* src = (t == 0 ? wq : t == 1 ? wk : wv) + L * SEG4 + o4;
        long d4 = ((long)L * QKVN + t * DIM) * (DIM / 4) + o4;
        store_split4(dh, dl, d4 * 2, *src);
    }
}

__global__ void split_w13_all(const float* __restrict__ w1, const float* __restrict__ w3,
                              bf162* __restrict__ dh, bf162* __restrict__ dl) {
    const int D4 = DIM / 4;
    long n4 = (long)NL * N13 * D4;
    long stride = (long)gridDim.x * blockDim.x;
    for (long i = (long)blockIdx.x * blockDim.x + threadIdx.x; i < n4; i += stride) {
        int col4 = (int)(i % D4);
        long rr = i / D4;
        int r = (int)(rr % N13);
        int L = (int)(rr / N13);
        int j = r >> 1, t = r & 1;
        float4 v = make_float4(0.f, 0.f, 0.f, 0.f);
        if (j < HIDDEN) {
            const float* s = (t ? w3 : w1) + ((long)L * HIDDEN + j) * DIM + col4 * 4;
            v = *(const float4*)s;
        }
        store_split4(dh, dl, i * 2, v);
    }
}

__global__ void split2_pad_kernel(const float* __restrict__ src,
                                  bf162* __restrict__ dh, bf162* __restrict__ dl,
                                  int rows, int Ks, int Kd) {
    long n2 = (long)rows * (Kd / 2);
    long stride = (long)gridDim.x * blockDim.x;
    for (long i = (long)blockIdx.x * blockDim.x + threadIdx.x; i < n2; i += stride) {
        int r  = (int)(i / (Kd / 2));
        int c2 = (int)(i - (long)r * (Kd / 2));
        float2 v = make_float2(0.f, 0.f);
        if (c2 * 2 + 1 < Ks)
            v = *reinterpret_cast<const float2*>(src + (long)r * Ks + c2 * 2);
        bf16 h0, l0, h1, l1;
        split1(v.x, h0, l0); split1(v.y, h1, l1);
        dh[i] = __halves2bfloat162(h0, h1);
        dl[i] = __halves2bfloat162(l0, l1);
    }
}

// cos/sin table: same math as the old rope kernel
__global__ void rope_table_kernel(float2* __restrict__ tab) {
    int i = blockIdx.x * blockDim.x + threadIdx.x;
    if (i >= SEQ * (HD / 2)) return;
    int s = i >> 5, p = i & 31;
    float freq = powf(THETA, -(2.0f * (float)p) / (float)HD);
    float ang  = (float)s * freq;
    tab[i] = make_float2(cosf(ang), sinf(ang));
}

__global__ void embed_kernel(const int* __restrict__ tokens,
                             const float* __restrict__ emb,
                             float* __restrict__ h) {
    int i = blockIdx.x * blockDim.x + threadIdx.x;
    if (i < SEQ * DIM) {
        int s = i / DIM, d = i - s * DIM;
        h[i] = emb[(long)tokens[s] * DIM + d];
    }
}

__global__ void rmsnorm_split_kernel(const float* __restrict__ x,
                                     const float* __restrict__ w,
                                     bf16* __restrict__ yh, bf16* __restrict__ yl) {
    int row = blockIdx.x;
    const float2* xr = (const float2*)(x + (long)row * DIM);
    const float2* w2p = (const float2*)w;
    float ss = 0.f;
    #pragma unroll
    for (int d = threadIdx.x; d < DIM / 2; d += 256) {
        float2 t = xr[d];
        ss += t.x * t.x + t.y * t.y;
    }
    #pragma unroll
    for (int off = 16; off; off >>= 1) ss += __shfl_xor_sync(0xffffffffu, ss, off);
    __shared__ float sred[8];
    if ((threadIdx.x & 31) == 0) sred[threadIdx.x >> 5] = ss;
    __syncthreads();
    __shared__ float s_inv;
    if (threadIdx.x == 0) {
        float tot = 0.f;
        #pragma unroll
        for (int i = 0; i < 8; i++) tot += sred[i];
        s_inv = rsqrtf(tot / (float)DIM + 1e-6f);
    }
    __syncthreads();
    float inv = s_inv;
    bf162* yh2 = (bf162*)(yh + (long)row * DIM);
    bf162* yl2 = (bf162*)(yl + (long)row * DIM);
    for (int d = threadIdx.x; d < DIM / 2; d += 256) {
        float2 t = xr[d], ww = w2p[d];
        float v0 = t.x * inv * ww.x, v1 = t.y * inv * ww.y;
        bf16 h0, l0, h1, l1;
        split1(v0, h0, l0); split1(v1, h1, l1);
        yh2[d] = __halves2bfloat162(h0, h1);
        yl2[d] = __halves2bfloat162(l0, l1);
    }
}

// ---------------- flash attention (R12 exact form) ----------------
#define BQ 16
__global__ __launch_bounds__(32 * BQ)
void attn_kernel(const float* __restrict__ qkv,
                 bf16* __restrict__ ohp, bf16* __restrict__ olp) {
    int h    = blockIdx.y;
    int q0   = blockIdx.x * BQ;
    int warp = threadIdx.x >> 5;
    int lane = threadIdx.x & 31;
    int qi   = q0 + warp;

    __shared__ float Ks[64][HD + 1];
    __shared__ float Vs[64][HD + 1];
    __shared__ float Qs[BQ][HD];

    Qs[warp][lane]      = qkv[(long)qi * QKVN + h * HD + lane];
    Qs[warp][lane + 32] = qkv[(long)qi * QKVN + h * HD + lane + 32];

    float m = -INFINITY, l = 0.f, o0 = 0.f, o1 = 0.f;
    int kend = q0 + BQ;

    for (int t0 = 0; t0 < kend; t0 += 64) {
        __syncthreads();
        for (int idx = threadIdx.x; idx < 64 * HD; idx += 32 * BQ) {
            int kj = idx >> 6, d = idx & 63;
            long row = (long)(t0 + kj) * QKVN + h * HD + d;
            Ks[kj][d] = qkv[row + DIM];
            Vs[kj][d] = qkv[row + 2 * DIM];
        }
        __syncthreads();

        float s0 = 0.f, s1 = 0.f;
        #pragma unroll
        for (int d = 0; d < HD; d++) {
            float qd = Qs[warp][d];
            s0 = fmaf(qd, Ks[lane][d],      s0);
            s1 = fmaf(qd, Ks[lane + 32][d], s1);
        }
        s0 *= ATT_SCALE; s1 *= ATT_SCALE;
        if (t0 + lane      > qi) s0 = -INFINITY;
        if (t0 + lane + 32 > qi) s1 = -INFINITY;

        float mt = fmaxf(s0, s1);
        #pragma unroll
        for (int off = 16; off; off >>= 1)
            mt = fmaxf(mt, __shfl_xor_sync(0xffffffffu, mt, off));
        float mnew  = fmaxf(m, mt);
        float alpha = __expf(m - mnew);
        float p0 = __expf(s0 - mnew);
        float p1 = __expf(s1 - mnew);
        float lsum = p0 + p1;
        #pragma unroll
        for (int off = 16; off; off >>= 1)
            lsum += __shfl_xor_sync(0xffffffffu, lsum, off);
        l = l * alpha + lsum;
        m = mnew;
        o0 *= alpha; o1 *= alpha;

        #pragma unroll
        for (int j = 0; j < 32; j++) {
            float pa = __shfl_sync(0xffffffffu, p0, j);
            float pb = __shfl_sync(0xffffffffu, p1, j);
            o0 = fmaf(pa, Vs[j][lane],           o0);
            o0 = fmaf(pb, Vs[j + 32][lane],      o0);
            o1 = fmaf(pa, Vs[j][lane + 32],      o1);
            o1 = fmaf(pb, Vs[j + 32][lane + 32], o1);
        }
    }
    float inv = 1.f / l;
    float v0 = o0 * inv, v1 = o1 * inv;
    bf16 hh, ll;
    long base = (long)qi * DIM + h * HD;
    split1(v0, hh, ll); ohp[base + lane]      = hh; olp[base + lane]      = ll;
    split1(v1, hh, ll); ohp[base + lane + 32] = hh; olp[base + lane + 32] = ll;
}

// ================= templated bf16x3 mma.sync GEMM, 3-stage, swizzled smem =================
// EPI=0: fp32 out (+res). EPI=1: silu(v0)*v1 -> bf16 hi/lo planes. EPI=2: rope on q/k cols.
__device__ __forceinline__ void mma_bf16(float* d, const uint32_t* a, const uint32_t* b) {
    asm volatile(
        "mma.sync.aligned.m16n8k16.row.col.f32.bf16.bf16.f32 "
        "{%0,%1,%2,%3}, {%4,%5,%6,%7}, {%8,%9}, {%0,%1,%2,%3};"
        : "+f"(d[0]), "+f"(d[1]), "+f"(d[2]), "+f"(d[3])
        : "r"(a[0]), "r"(a[1]), "r"(a[2]), "r"(a[3]), "r"(b[0]), "r"(b[1]));
}
__device__ __forceinline__ void ldmx4(uint32_t* r, uint32_t addr) {
    asm volatile("ldmatrix.sync.aligned.m8n8.x4.shared.b16 {%0,%1,%2,%3}, [%4];"
                 : "=r"(r[0]), "=r"(r[1]), "=r"(r[2]), "=r"(r[3]) : "r"(addr));
}
__device__ __forceinline__ void cpa16(uint32_t dst, const void* src) {
    asm volatile("cp.async.cg.shared.global [%0], [%1], 16;" :: "r"(dst), "l"(src));
}

template<int BM, int WM, int WN, int THREADS, int MAXB, int K, int EPI>
__global__ __launch_bounds__(THREADS, MAXB)
void gemm_bf3(const bf16* __restrict__ Ah, const bf16* __restrict__ Al,
              const bf16* __restrict__ Bh, const bf16* __restrict__ Bl,
              const float* __restrict__ res, float* __restrict__ C,
              bf16* __restrict__ Eh, bf16* __restrict__ El,
              const float2* __restrict__ rtab,
              int N) {
    const int BN = BM;
    const int WARPS_N = BN / WN;
    const int MT = WM / 16;
    const int NT = WN / 8;
    const int PB = BM * 64;
    const int SB = 4 * PB;
    const int KT = K / 32;
    const int CPT = 16 * BM / THREADS;

    extern __shared__ char smc[];
    uint32_t sbase = (uint32_t)__cvta_generic_to_shared(smc);

    int bm = blockIdx.y * BM;
    int bn = blockIdx.x * BN;
    int tid  = threadIdx.x;
    int warp = tid >> 5, lane = tid & 31;
    int wm = (warp / WARPS_N) * WM;
    int wn = (warp % WARPS_N) * WN;
    int g  = lane >> 2, tg = lane & 3;
    int rr = lane & 7, q = lane >> 3;

    int aRowL = wm + rr + 8 * (q & 1);
    int bRowL = wn + rr + 8 * (q >> 1);
    uint32_t aRowOff = (uint32_t)aRowL * 64;
    uint32_t bRowOff = (uint32_t)bRowL * 64;
    uint32_t swA = (uint32_t)((aRowL >> 1) & 3);
    uint32_t swB = (uint32_t)((bRowL >> 1) & 3);
    uint32_t cAk[2], cBk[2];
    #pragma unroll
    for (int ks = 0; ks < 2; ks++) {
        cAk[ks] = ((uint32_t)(2 * ks + (q >> 1)) ^ swA) << 4;
        cBk[ks] = ((uint32_t)(2 * ks + (q & 1))  ^ swB) << 4;
    }

    const bf16* pl[4] = { Ah, Al, Bh, Bl };
    uint32_t dstoff[CPT];
    const bf16* srcb[CPT];
    #pragma unroll
    for (int t = 0; t < CPT; t++) {
        int cid = tid + t * THREADS;
        int p   = cid / (4 * BM);
        int rem = cid - p * (4 * BM);
        int row = rem >> 2, ch = rem & 3;
        dstoff[t] = (uint32_t)p * PB + (uint32_t)row * 64
                  + (((uint32_t)ch ^ (((uint32_t)row >> 1) & 3)) << 4);
        int rowG = ((p < 2) ? bm : bn) + row;
        srcb[t] = pl[p] + (long)rowG * K + ch * 8;
    }

    float acc[MT][NT][4];
    #pragma unroll
    for (int mi = 0; mi < MT; mi++)
        #pragma unroll
        for (int ni = 0; ni < NT; ni++)
            #pragma unroll
            for (int r = 0; r < 4; r++) acc[mi][ni][r] = 0.f;

    auto fill = [&](int s, int k0) {
        uint32_t st = sbase + (uint32_t)s * SB;
        #pragma unroll
        for (int t = 0; t < CPT; t++)
            cpa16(st + dstoff[t], srcb[t] + k0);
        asm volatile("cp.async.commit_group;");
    };

    fill(0, 0);
    fill(1, 32);

    #pragma unroll 3
    for (int kt = 0; kt < KT; kt++) {
        if (kt + 1 < KT) asm volatile("cp.async.wait_group 1;");
        else             asm volatile("cp.async.wait_group 0;");
        __syncthreads();

        if (kt + 2 < KT) fill((kt + 2) % 3, (kt + 2) * 32);

        uint32_t st  = sbase + (uint32_t)(kt % 3) * SB;
        uint32_t pAH = st;
        uint32_t pAL = st + PB;
        uint32_t pBH = st + 2 * PB;
        uint32_t pBL = st + 3 * PB;

        #pragma unroll
        for (int ks = 0; ks < 2; ks++) {
            uint32_t afH[MT][4], bfH[NT][2], bfX[NT][2];
            #pragma unroll
            for (int mi = 0; mi < MT; mi++)
                ldmx4(afH[mi], pAH + aRowOff + (uint32_t)mi * 1024 + cAk[ks]);
            #pragma unroll
            for (int n2 = 0; n2 < NT / 2; n2++) {
                uint32_t t[4];
                ldmx4(t, pBH + bRowOff + (uint32_t)n2 * 1024 + cBk[ks]);
                bfH[2 * n2][0] = t[0]; bfH[2 * n2][1] = t[1];
                bfH[2 * n2 + 1][0] = t[2]; bfH[2 * n2 + 1][1] = t[3];
            }
            #pragma unroll
            for (int mi = 0; mi < MT; mi++)
                #pragma unroll
                for (int ni = 0; ni < NT; ni++)
                    mma_bf16(acc[mi][ni], afH[mi], bfH[ni]);

            #pragma unroll
            for (int n2 = 0; n2 < NT / 2; n2++) {
                uint32_t t[4];
                ldmx4(t, pBL + bRowOff + (uint32_t)n2 * 1024 + cBk[ks]);
                bfX[2 * n2][0] = t[0]; bfX[2 * n2][1] = t[1];
                bfX[2 * n2 + 1][0] = t[2]; bfX[2 * n2 + 1][1] = t[3];
            }
            #pragma unroll
            for (int mi = 0; mi < MT; mi++)
                #pragma unroll
                for (int ni = 0; ni < NT; ni++)
                    mma_bf16(acc[mi][ni], afH[mi], bfX[ni]);

            #pragma unroll
            for (int mi = 0; mi < MT; mi++)
                ldmx4(afH[mi], pAL + aRowOff + (uint32_t)mi * 1024 + cAk[ks]);
            #pragma unroll
            for (int mi = 0; mi < MT; mi++)
                #pragma unroll
                for (int ni = 0; ni < NT; ni++)
                    mma_bf16(acc[mi][ni], afH[mi], bfH[ni]);
        }
    }

    #pragma unroll
    for (int mi = 0; mi < MT; mi++) {
        int row0 = bm + wm + mi * 16 + g;
        #pragma unroll
        for (int ni = 0; ni < NT; ni++) {
            int col = bn + wn + ni * 8 + tg * 2;
            #pragma unroll
            for (int half = 0; half < 2; half++) {
                int row = row0 + half * 8;
                float v0 = acc[mi][ni][half * 2 + 0];
                float v1 = acc[mi][ni][half * 2 + 1];
                if (EPI == 0 || EPI == 2) {
                    if (EPI == 2 && col < 2 * DIM) {
                        // rope rotation on the adjacent (even, odd) pair
                        float2 cs = rtab[row * (HD / 2) + ((col & 63) >> 1)];
                        float a = v0, b = v1;
                        v0 = a * cs.x - b * cs.y;
                        v1 = a * cs.y + b * cs.x;
                    }
                    long idx = (long)row * N + col;
                    if (EPI == 0 && res) { v0 += res[idx]; v1 += res[idx + 1]; }
                    C[idx]     = v0;
                    C[idx + 1] = v1;
                } else {
                    float v = (v0 / (1.f + __expf(-v0))) * v1;
                    bf16 hh, ll; split1(v, hh, ll);
                    long idx = (long)row * (N / 2) + (col >> 1);
                    Eh[idx] = hh;
                    El[idx] = ll;
                }
            }
        }
    }
}

#define GB768      gemm_bf3<128, 64, 32, 256, 2, 768, 0>
#define GB768_ROPE gemm_bf3<128, 64, 32, 256, 2, 768, 2>
#define GB768_SILU gemm_bf3<128, 64, 32, 256, 2, 768, 1>
#define GS768      gemm_bf3< 64, 32, 32, 128, 4, 768, 0>
#define GS2048     gemm_bf3< 64, 32, 32, 128, 4, 2048, 0>
#define SMEM_B  (3 * 4 * 128 * 64)   // 98304
#define SMEM_S  (3 * 4 * 64 * 64)    // 49152

static inline unsigned gblocks(long n, int cap) {
    long b = (n + 255) / 256;
    if (b > cap) b = cap;
    return (unsigned)b;
}

extern "C" void kernel_launch(void* const* d_in, const int* in_sizes, int n_in,
                              void* d_out, int out_size) {
    const int*   tokens   = (const int*)  d_in[0];
    const float* emb      = (const float*)d_in[1];
    const float* wq       = (const float*)d_in[2];
    const float* wk       = (const float*)d_in[3];
    const float* wv       = (const float*)d_in[4];
    const float* wo       = (const float*)d_in[5];
    const float* w1       = (const float*)d_in[6];
    const float* w2       = (const float*)d_in[7];
    const float* w3       = (const float*)d_in[8];
    const float* attn_nw  = (const float*)d_in[9];
    const float* ffn_nw   = (const float*)d_in[10];
    const float* norm_w   = (const float*)d_in[11];
    const float* out_w    = (const float*)d_in[12];
    float* out = (float*)d_out;

    float *h, *qkv;
    float2* rtab;
    cudaGetSymbolAddress((void**)&h,    g_h);
    cudaGetSymbolAddress((void**)&qkv,  g_qkv);
    cudaGetSymbolAddress((void**)&rtab, g_rope);

    bf16 *wqkvh, *wqkvl, *woh, *wol, *w13h, *w13l, *w2h, *w2l, *owh, *owl;
    bf16 *xh, *xl, *oh, *ol, *h1h, *h1l;
    cudaGetSymbolAddress((void**)&wqkvh, g_wqkv_h); cudaGetSymbolAddress((void**)&wqkvl, g_wqkv_l);
    cudaGetSymbolAddress((void**)&woh,   g_wo_h);   cudaGetSymbolAddress((void**)&wol,   g_wo_l);
    cudaGetSymbolAddress((void**)&w13h,  g_w13_h);  cudaGetSymbolAddress((void**)&w13l,  g_w13_l);
    cudaGetSymbolAddress((void**)&w2h,   g_w2_h);   cudaGetSymbolAddress((void**)&w2l,   g_w2_l);
    cudaGetSymbolAddress((void**)&owh,   g_ow_h);   cudaGetSymbolAddress((void**)&owl,   g_ow_l);
    cudaGetSymbolAddress((void**)&xh,  g_xh);  cudaGetSymbolAddress((void**)&xl,  g_xl);
    cudaGetSymbolAddress((void**)&oh,  g_oh);  cudaGetSymbolAddress((void**)&ol,  g_ol);
    cudaGetSymbolAddress((void**)&h1h, g_h1h); cudaGetSymbolAddress((void**)&h1l, g_h1l);

    cudaFuncSetAttribute(GB768,      cudaFuncAttributeMaxDynamicSharedMemorySize, SMEM_B);
    cudaFuncSetAttribute(GB768_ROPE, cudaFuncAttributeMaxDynamicSharedMemorySize, SMEM_B);
    cudaFuncSetAttribute(GB768_SILU, cudaFuncAttributeMaxDynamicSharedMemorySize, SMEM_B);
    cudaFuncSetAttribute(GS768,      cudaFuncAttributeMaxDynamicSharedMemorySize, SMEM_S);
    cudaFuncSetAttribute(GS2048,     cudaFuncAttributeMaxDynamicSharedMemorySize, SMEM_S);

    // ---- one-time prep: weight splits + rope table ----
    split_qkv_all<<<gblocks((long)NL * 3 * DIM * DIM / 4, 16384), 256>>>(
        (const float4*)wq, (const float4*)wk, (const float4*)wv,
        (bf162*)wqkvh, (bf162*)wqkvl);
    split4_kernel<<<gblocks((long)NL * DIM * DIM / 4, 16384), 256>>>(
        (const float4*)wo, (bf162*)woh, (bf162*)wol, (long)NL * DIM * DIM / 4);
    split_w13_all<<<gblocks((long)NL * N13 * DIM / 4, 16384), 256>>>(
        w1, w3, (bf162*)w13h, (bf162*)w13l);
    split2_pad_kernel<<<gblocks((long)NL * DIM * HIDP / 2, 16384), 256>>>(
        w2, (bf162*)w2h, (bf162*)w2l, NL * DIM, HIDDEN, HIDP);
    split4_kernel<<<gblocks((long)VOCAB * DIM / 4, 16384), 256>>>(
        (const float4*)out_w, (bf162*)owh, (bf162*)owl, (long)VOCAB * DIM / 4);
    rope_table_kernel<<<(SEQ * (HD / 2) + 255) / 256, 256>>>(rtab);

    // ---- forward ----
    embed_kernel<<<(SEQ * DIM + 255) / 256, 256>>>(tokens, emb, h);

    for (int L = 0; L < NL; L++) {
        rmsnorm_split_kernel<<<SEQ, 256>>>(h, attn_nw + L * DIM, xh, xl);

        // QKV GEMM with fused RoPE (q and k columns rotated in-register)
        GB768_ROPE<<<dim3(QKVN / 128, SEQ / 128), 256, SMEM_B>>>(
            xh, xl, wqkvh + (long)L * QKVN * DIM, wqkvl + (long)L * QKVN * DIM,
            nullptr, qkv, nullptr, nullptr, rtab, QKVN);

        attn_kernel<<<dim3(SEQ / BQ, NH), 32 * BQ>>>(qkv, oh, ol);

        GS768<<<dim3(DIM / 64, SEQ / 64), 128, SMEM_S>>>(
            oh, ol, woh + (long)L * DIM * DIM, wol + (long)L * DIM * DIM,
            h, h, nullptr, nullptr, nullptr, DIM);

        rmsnorm_split_kernel<<<SEQ, 256>>>(h, ffn_nw + L * DIM, xh, xl);

        GB768_SILU<<<dim3(N13 / 128, SEQ / 128), 256, SMEM_B>>>(
            xh, xl, w13h + (long)L * N13 * DIM, w13l + (long)L * N13 * DIM,
            nullptr, nullptr, h1h, h1l, nullptr, N13);

        GS2048<<<dim3(DIM / 64, SEQ / 64), 128, SMEM_S>>>(
            h1h, h1l, w2h + (long)L * DIM * HIDP, w2l + (long)L * DIM * HIDP,
            h, h, nullptr, nullptr, nullptr, DIM);
    }

    rmsnorm_split_kernel<<<SEQ, 256>>>(h, norm_w, xh, xl);

    GB768<<<dim3(VOCAB / 128, SEQ / 128), 256, SMEM_B>>>(
        xh, xl, owh, owl, nullptr, out, nullptr, nullptr, nullptr, VOCAB);
}

// round 17
// speedup vs baseline: 1.2241x; 1.1722x over previous
#include <cuda_runtime.h>
#include <cuda_bf16.h>
#include <math.h>
#include <stdint.h>

#define SEQ     2048
#define DIM     768
#define NH      12
#define HD      64
#define HIDDEN  2042
#define HIDP    2048
#define N13     4096
#define QKVN    2304
#define VOCAB   32000
#define NL      4
#define THETA   10000.0f
#define ATT_SCALE 0.125f

typedef __nv_bfloat16 bf16;
typedef __nv_bfloat162 bf162;

// ---------------- fp32 scratch ----------------
__device__ float g_h  [SEQ * DIM];
__device__ float g_qkv[SEQ * QKVN];
__device__ float2 g_rope[SEQ * (HD / 2)];

// ---------------- bf16 hi/lo planes (16B aligned) ----------------
__device__ __align__(16) bf16 g_wqkv_h[NL * QKVN * DIM],  g_wqkv_l[NL * QKVN * DIM];
__device__ __align__(16) bf16 g_wo_h  [NL * DIM * DIM],   g_wo_l  [NL * DIM * DIM];
__device__ __align__(16) bf16 g_w13_h [NL * N13 * DIM],   g_w13_l [NL * N13 * DIM];
__device__ __align__(16) bf16 g_w2_h  [NL * DIM * HIDP],  g_w2_l  [NL * DIM * HIDP];
__device__ __align__(16) bf16 g_ow_h  [VOCAB * DIM],      g_ow_l  [VOCAB * DIM];
__device__ __align__(16) bf16 g_xh [SEQ * DIM],  g_xl [SEQ * DIM];
__device__ __align__(16) bf16 g_oh [SEQ * DIM],  g_ol [SEQ * DIM];
__device__ __align__(16) bf16 g_h1h[SEQ * HIDP], g_h1l[SEQ * HIDP];

// ---------------- helpers ----------------
__device__ __forceinline__ void split1(float v, bf16& h, bf16& l) {
    h = __float2bfloat16(v);
    l = __float2bfloat16(v - __bfloat162float(h));
}

__device__ __forceinline__ void store_split4(bf162* dh, bf162* dl, long d2, float4 v) {
    bf16 h0, l0, h1, l1, h2, l2, h3, l3;
    split1(v.x, h0, l0); split1(v.y, h1, l1);
    split1(v.z, h2, l2); split1(v.w, h3, l3);
    dh[d2]     = __halves2bfloat162(h0, h1);
    dh[d2 + 1] = __halves2bfloat162(h2, h3);
    dl[d2]     = __halves2bfloat162(l0, l1);
    dl[d2 + 1] = __halves2bfloat162(l2, l3);
}

__global__ void split4_kernel(const float4* __restrict__ src,
                              bf162* __restrict__ dh, bf162* __restrict__ dl,
                              long n4) {
    long stride = (long)gridDim.x * blockDim.x;
    for (long i = (long)blockIdx.x * blockDim.x + threadIdx.x; i < n4; i += stride)
        store_split4(dh, dl, i * 2, src[i]);
}

__global__ void split_qkv_all(const float4* __restrict__ wq, const float4* __restrict__ wk,
                              const float4* __restrict__ wv,
                              bf162* __restrict__ dh, bf162* __restrict__ dl) {
    const long SEG4 = (long)DIM * DIM / 4;
    long n4 = NL * 3 * SEG4;
    long stride = (long)gridDim.x * blockDim.x;
    for (long i = (long)blockIdx.x * blockDim.x + threadIdx.x; i < n4; i += stride) {
        long seg = i / SEG4;
        int L = (int)(seg / 3), t = (int)(seg % 3);
        long o4 = i - seg * SEG4;
        const float4* src = (t == 0 ? wq : t == 1 ? wk : wv) + L * SEG4 + o4;
        long d4 = ((long)L * QKVN + t * DIM) * (DIM / 4) + o4;
        store_split4(dh, dl, d4 * 2, *src);
    }
}

__global__ void split_w13_all(const float* __restrict__ w1, const float* __restrict__ w3,
                              bf162* __restrict__ dh, bf162* __restrict__ dl) {
    const int D4 = DIM / 4;
    long n4 = (long)NL * N13 * D4;
    long stride = (long)gridDim.x * blockDim.x;
    for (long i = (long)blockIdx.x * blockDim.x + threadIdx.x; i < n4; i += stride) {
        int col4 = (int)(i % D4);
        long rr = i / D4;
        int r = (int)(rr % N13);
        int L = (int)(rr / N13);
        int j = r >> 1, t = r & 1;
        float4 v = make_float4(0.f, 0.f, 0.f, 0.f);
        if (j < HIDDEN) {
            const float* s = (t ? w3 : w1) + ((long)L * HIDDEN + j) * DIM + col4 * 4;
            v = *(const float4*)s;
        }
        store_split4(dh, dl, i * 2, v);
    }
}

__global__ void split2_pad_kernel(const float* __restrict__ src,
                                  bf162* __restrict__ dh, bf162* __restrict__ dl,
                                  int rows, int Ks, int Kd) {
    long n2 = (long)rows * (Kd / 2);
    long stride = (long)gridDim.x * blockDim.x;
    for (long i = (long)blockIdx.x * blockDim.x + threadIdx.x; i < n2; i += stride) {
        int r  = (int)(i / (Kd / 2));
        int c2 = (int)(i - (long)r * (Kd / 2));
        float2 v = make_float2(0.f, 0.f);
        if (c2 * 2 + 1 < Ks)
            v = *reinterpret_cast<const float2*>(src + (long)r * Ks + c2 * 2);
        bf16 h0, l0, h1, l1;
        split1(v.x, h0, l0); split1(v.y, h1, l1);
        dh[i] = __halves2bfloat162(h0, h1);
        dl[i] = __halves2bfloat162(l0, l1);
    }
}

__global__ void rope_table_kernel(float2* __restrict__ tab) {
    int i = blockIdx.x * blockDim.x + threadIdx.x;
    if (i >= SEQ * (HD / 2)) return;
    int s = i >> 5, p = i & 31;
    float freq = powf(THETA, -(2.0f * (float)p) / (float)HD);
    float ang  = (float)s * freq;
    tab[i] = make_float2(cosf(ang), sinf(ang));
}

__global__ void embed_kernel(const int* __restrict__ tokens,
                             const float* __restrict__ emb,
                             float* __restrict__ h) {
    int i = blockIdx.x * blockDim.x + threadIdx.x;
    if (i < SEQ * DIM) {
        int s = i / DIM, d = i - s * DIM;
        h[i] = emb[(long)tokens[s] * DIM + d];
    }
}

__global__ void rmsnorm_split_kernel(const float* __restrict__ x,
                                     const float* __restrict__ w,
                                     bf16* __restrict__ yh, bf16* __restrict__ yl) {
    int row = blockIdx.x;
    const float2* xr = (const float2*)(x + (long)row * DIM);
    const float2* w2p = (const float2*)w;
    float ss = 0.f;
    #pragma unroll
    for (int d = threadIdx.x; d < DIM / 2; d += 256) {
        float2 t = xr[d];
        ss += t.x * t.x + t.y * t.y;
    }
    #pragma unroll
    for (int off = 16; off; off >>= 1) ss += __shfl_xor_sync(0xffffffffu, ss, off);
    __shared__ float sred[8];
    if ((threadIdx.x & 31) == 0) sred[threadIdx.x >> 5] = ss;
    __syncthreads();
    __shared__ float s_inv;
    if (threadIdx.x == 0) {
        float tot = 0.f;
        #pragma unroll
        for (int i = 0; i < 8; i++) tot += sred[i];
        s_inv = rsqrtf(tot / (float)DIM + 1e-6f);
    }
    __syncthreads();
    float inv = s_inv;
    bf162* yh2 = (bf162*)(yh + (long)row * DIM);
    bf162* yl2 = (bf162*)(yl + (long)row * DIM);
    for (int d = threadIdx.x; d < DIM / 2; d += 256) {
        float2 t = xr[d], ww = w2p[d];
        float v0 = t.x * inv * ww.x, v1 = t.y * inv * ww.y;
        bf16 h0, l0, h1, l1;
        split1(v0, h0, l0); split1(v1, h1, l1);
        yh2[d] = __halves2bfloat162(h0, h1);
        yl2[d] = __halves2bfloat162(l0, l1);
    }
}

// ---------------- flash attention: 2 queries per warp, BQ=32, 512 threads ----------------
#define BQ 32
__global__ __launch_bounds__(512)
void attn_kernel(const float* __restrict__ qkv,
                 bf16* __restrict__ ohp, bf16* __restrict__ olp) {
    int h    = blockIdx.y;
    int q0   = blockIdx.x * BQ;
    int warp = threadIdx.x >> 5;
    int lane = threadIdx.x & 31;
    int qa   = q0 + warp * 2;
    int qb   = qa + 1;

    __shared__ float Ks[64][HD + 1];
    __shared__ float Vs[64][HD + 1];
    __shared__ float Qs[BQ][HD];

    Qs[warp * 2][lane]          = qkv[(long)qa * QKVN + h * HD + lane];
    Qs[warp * 2][lane + 32]     = qkv[(long)qa * QKVN + h * HD + lane + 32];
    Qs[warp * 2 + 1][lane]      = qkv[(long)qb * QKVN + h * HD + lane];
    Qs[warp * 2 + 1][lane + 32] = qkv[(long)qb * QKVN + h * HD + lane + 32];

    float ma = -INFINITY, la = 0.f, o0a = 0.f, o1a = 0.f;
    float mb = -INFINITY, lb = 0.f, o0b = 0.f, o1b = 0.f;
    int kend = q0 + BQ;

    for (int t0 = 0; t0 < kend; t0 += 64) {
        __syncthreads();
        for (int idx = threadIdx.x; idx < 64 * HD; idx += 512) {
            int kj = idx >> 6, d = idx & 63;
            long row = (long)(t0 + kj) * QKVN + h * HD + d;
            Ks[kj][d] = qkv[row + DIM];
            Vs[kj][d] = qkv[row + 2 * DIM];
        }
        __syncthreads();

        float s0a = 0.f, s1a = 0.f, s0b = 0.f, s1b = 0.f;
        #pragma unroll
        for (int d = 0; d < HD; d++) {
            float qda = Qs[warp * 2][d];
            float qdb = Qs[warp * 2 + 1][d];
            float k0  = Ks[lane][d];
            float k1  = Ks[lane + 32][d];
            s0a = fmaf(qda, k0, s0a);
            s1a = fmaf(qda, k1, s1a);
            s0b = fmaf(qdb, k0, s0b);
            s1b = fmaf(qdb, k1, s1b);
        }
        s0a *= ATT_SCALE; s1a *= ATT_SCALE;
        s0b *= ATT_SCALE; s1b *= ATT_SCALE;
        if (t0 + lane      > qa) s0a = -INFINITY;
        if (t0 + lane + 32 > qa) s1a = -INFINITY;
        if (t0 + lane      > qb) s0b = -INFINITY;
        if (t0 + lane + 32 > qb) s1b = -INFINITY;

        // softmax update, query a
        float mta = fmaxf(s0a, s1a);
        #pragma unroll
        for (int off = 16; off; off >>= 1)
            mta = fmaxf(mta, __shfl_xor_sync(0xffffffffu, mta, off));
        float mna = fmaxf(ma, mta);
        float ala = __expf(ma - mna);
        float p0a = __expf(s0a - mna);
        float p1a = __expf(s1a - mna);
        float lsa = p0a + p1a;
        #pragma unroll
        for (int off = 16; off; off >>= 1)
            lsa += __shfl_xor_sync(0xffffffffu, lsa, off);
        la = la * ala + lsa;
        ma = mna;
        o0a *= ala; o1a *= ala;

        // softmax update, query b
        float mtb = fmaxf(s0b, s1b);
        #pragma unroll
        for (int off = 16; off; off >>= 1)
            mtb = fmaxf(mtb, __shfl_xor_sync(0xffffffffu, mtb, off));
        float mnb = fmaxf(mb, mtb);
        float alb = __expf(mb - mnb);
        float p0b = __expf(s0b - mnb);
        float p1b = __expf(s1b - mnb);
        float lsb = p0b + p1b;
        #pragma unroll
        for (int off = 16; off; off >>= 1)
            lsb += __shfl_xor_sync(0xffffffffu, lsb, off);
        lb = lb * alb + lsb;
        mb = mnb;
        o0b *= alb; o1b *= alb;

        #pragma unroll
        for (int j = 0; j < 32; j++) {
            float va0 = Vs[j][lane];
            float va1 = Vs[j + 32][lane];
            float vb0 = Vs[j][lane + 32];
            float vb1 = Vs[j + 32][lane + 32];
            float paa = __shfl_sync(0xffffffffu, p0a, j);
            float pba = __shfl_sync(0xffffffffu, p1a, j);
            float pab = __shfl_sync(0xffffffffu, p0b, j);
            float pbb = __shfl_sync(0xffffffffu, p1b, j);
            o0a = fmaf(paa, va0, o0a); o0a = fmaf(pba, va1, o0a);
            o1a = fmaf(paa, vb0, o1a); o1a = fmaf(pba, vb1, o1a);
            o0b = fmaf(pab, va0, o0b); o0b = fmaf(pbb, va1, o0b);
            o1b = fmaf(pab, vb0, o1b); o1b = fmaf(pbb, vb1, o1b);
        }
    }
    bf16 hh, ll;
    {
        float inv = 1.f / la;
        long base = (long)qa * DIM + h * HD;
        split1(o0a * inv, hh, ll); ohp[base + lane]      = hh; olp[base + lane]      = ll;
        split1(o1a * inv, hh, ll); ohp[base + lane + 32] = hh; olp[base + lane + 32] = ll;
    }
    {
        float inv = 1.f / lb;
        long base = (long)qb * DIM + h * HD;
        split1(o0b * inv, hh, ll); ohp[base + lane]      = hh; olp[base + lane]      = ll;
        split1(o1b * inv, hh, ll); ohp[base + lane + 32] = hh; olp[base + lane + 32] = ll;
    }
}

// ================= templated bf16x3 mma.sync GEMM, 3-stage, swizzled smem =================
// EPI=0: fp32 out (+res). EPI=1: silu(v0)*v1 -> bf16 hi/lo planes. EPI=2: rope on q/k cols.
__device__ __forceinline__ void mma_bf16(float* d, const uint32_t* a, const uint32_t* b) {
    asm volatile(
        "mma.sync.aligned.m16n8k16.row.col.f32.bf16.bf16.f32 "
        "{%0,%1,%2,%3}, {%4,%5,%6,%7}, {%8,%9}, {%0,%1,%2,%3};"
        : "+f"(d[0]), "+f"(d[1]), "+f"(d[2]), "+f"(d[3])
        : "r"(a[0]), "r"(a[1]), "r"(a[2]), "r"(a[3]), "r"(b[0]), "r"(b[1]));
}
__device__ __forceinline__ void ldmx4(uint32_t* r, uint32_t addr) {
    asm volatile("ldmatrix.sync.aligned.m8n8.x4.shared.b16 {%0,%1,%2,%3}, [%4];"
                 : "=r"(r[0]), "=r"(r[1]), "=r"(r[2]), "=r"(r[3]) : "r"(addr));
}
__device__ __forceinline__ void cpa16(uint32_t dst, const void* src) {
    asm volatile("cp.async.cg.shared.global [%0], [%1], 16;" :: "r"(dst), "l"(src));
}

template<int BM, int WM, int WN, int THREADS, int MAXB, int K, int EPI>
__global__ __launch_bounds__(THREADS, MAXB)
void gemm_bf3(const bf16* __restrict__ Ah, const bf16* __restrict__ Al,
              const bf16* __restrict__ Bh, const bf16* __restrict__ Bl,
              const float* __restrict__ res, float* __restrict__ C,
              bf16* __restrict__ Eh, bf16* __restrict__ El,
              const float2* __restrict__ rtab,
              int N) {
    const int BN = BM;
    const int WARPS_N = BN / WN;
    const int MT = WM / 16;
    const int NT = WN / 8;
    const int PB = BM * 64;
    const int SB = 4 * PB;
    const int KT = K / 32;
    const int CPT = 16 * BM / THREADS;

    extern __shared__ char smc[];
    uint32_t sbase = (uint32_t)__cvta_generic_to_shared(smc);

    int bm = blockIdx.y * BM;
    int bn = blockIdx.x * BN;
    int tid  = threadIdx.x;
    int warp = tid >> 5, lane = tid & 31;
    int wm = (warp / WARPS_N) * WM;
    int wn = (warp % WARPS_N) * WN;
    int g  = lane >> 2, tg = lane & 3;
    int rr = lane & 7, q = lane >> 3;

    int aRowL = wm + rr + 8 * (q & 1);
    int bRowL = wn + rr + 8 * (q >> 1);
    uint32_t aRowOff = (uint32_t)aRowL * 64;
    uint32_t bRowOff = (uint32_t)bRowL * 64;
    uint32_t swA = (uint32_t)((aRowL >> 1) & 3);
    uint32_t swB = (uint32_t)((bRowL >> 1) & 3);
    uint32_t cAk[2], cBk[2];
    #pragma unroll
    for (int ks = 0; ks < 2; ks++) {
        cAk[ks] = ((uint32_t)(2 * ks + (q >> 1)) ^ swA) << 4;
        cBk[ks] = ((uint32_t)(2 * ks + (q & 1))  ^ swB) << 4;
    }

    const bf16* pl[4] = { Ah, Al, Bh, Bl };
    uint32_t dstoff[CPT];
    const bf16* srcb[CPT];
    #pragma unroll
    for (int t = 0; t < CPT; t++) {
        int cid = tid + t * THREADS;
        int p   = cid / (4 * BM);
        int rem = cid - p * (4 * BM);
        int row = rem >> 2, ch = rem & 3;
        dstoff[t] = (uint32_t)p * PB + (uint32_t)row * 64
                  + (((uint32_t)ch ^ (((uint32_t)row >> 1) & 3)) << 4);
        int rowG = ((p < 2) ? bm : bn) + row;
        srcb[t] = pl[p] + (long)rowG * K + ch * 8;
    }

    float acc[MT][NT][4];
    #pragma unroll
    for (int mi = 0; mi < MT; mi++)
        #pragma unroll
        for (int ni = 0; ni < NT; ni++)
            #pragma unroll
            for (int r = 0; r < 4; r++) acc[mi][ni][r] = 0.f;

    auto fill = [&](int s, int k0) {
        uint32_t st = sbase + (uint32_t)s * SB;
        #pragma unroll
        for (int t = 0; t < CPT; t++)
            cpa16(st + dstoff[t], srcb[t] + k0);
        asm volatile("cp.async.commit_group;");
    };

    fill(0, 0);
    fill(1, 32);

    #pragma unroll 3
    for (int kt = 0; kt < KT; kt++) {
        if (kt + 1 < KT) asm volatile("cp.async.wait_group 1;");
        else             asm volatile("cp.async.wait_group 0;");
        __syncthreads();

        if (kt + 2 < KT) fill((kt + 2) % 3, (kt + 2) * 32);

        uint32_t st  = sbase + (uint32_t)(kt % 3) * SB;
        uint32_t pAH = st;
        uint32_t pAL = st + PB;
        uint32_t pBH = st + 2 * PB;
        uint32_t pBL = st + 3 * PB;

        #pragma unroll
        for (int ks = 0; ks < 2; ks++) {
            uint32_t afH[MT][4], bfH[NT][2], bfX[NT][2];
            #pragma unroll
            for (int mi = 0; mi < MT; mi++)
                ldmx4(afH[mi], pAH + aRowOff + (uint32_t)mi * 1024 + cAk[ks]);
            #pragma unroll
            for (int n2 = 0; n2 < NT / 2; n2++) {
                uint32_t t[4];
                ldmx4(t, pBH + bRowOff + (uint32_t)n2 * 1024 + cBk[ks]);
                bfH[2 * n2][0] = t[0]; bfH[2 * n2][1] = t[1];
                bfH[2 * n2 + 1][0] = t[2]; bfH[2 * n2 + 1][1] = t[3];
            }
            #pragma unroll
            for (int mi = 0; mi < MT; mi++)
                #pragma unroll
                for (int ni = 0; ni < NT; ni++)
                    mma_bf16(acc[mi][ni], afH[mi], bfH[ni]);

            #pragma unroll
            for (int n2 = 0; n2 < NT / 2; n2++) {
                uint32_t t[4];
                ldmx4(t, pBL + bRowOff + (uint32_t)n2 * 1024 + cBk[ks]);
                bfX[2 * n2][0] = t[0]; bfX[2 * n2][1] = t[1];
                bfX[2 * n2 + 1][0] = t[2]; bfX[2 * n2 + 1][1] = t[3];
            }
            #pragma unroll
            for (int mi = 0; mi < MT; mi++)
                #pragma unroll
                for (int ni = 0; ni < NT; ni++)
                    mma_bf16(acc[mi][ni], afH[mi], bfX[ni]);

            #pragma unroll
            for (int mi = 0; mi < MT; mi++)
                ldmx4(afH[mi], pAL + aRowOff + (uint32_t)mi * 1024 + cAk[ks]);
            #pragma unroll
            for (int mi = 0; mi < MT; mi++)
                #pragma unroll
                for (int ni = 0; ni < NT; ni++)
                    mma_bf16(acc[mi][ni], afH[mi], bfH[ni]);
        }
    }

    #pragma unroll
    for (int mi = 0; mi < MT; mi++) {
        int row0 = bm + wm + mi * 16 + g;
        #pragma unroll
        for (int ni = 0; ni < NT; ni++) {
            int col = bn + wn + ni * 8 + tg * 2;
            #pragma unroll
            for (int half = 0; half < 2; half++) {
                int row = row0 + half * 8;
                float v0 = acc[mi][ni][half * 2 + 0];
                float v1 = acc[mi][ni][half * 2 + 1];
                if (EPI == 0 || EPI == 2) {
                    if (EPI == 2 && col < 2 * DIM) {
                        float2 cs = rtab[row * (HD / 2) + ((col & 63) >> 1)];
                        float a = v0, b = v1;
                        v0 = a * cs.x - b * cs.y;
                        v1 = a * cs.y + b * cs.x;
                    }
                    long idx = (long)row * N + col;
                    if (EPI == 0 && res) { v0 += res[idx]; v1 += res[idx + 1]; }
                    C[idx]     = v0;
                    C[idx + 1] = v1;
                } else {
                    float v = (v0 / (1.f + __expf(-v0))) * v1;
                    bf16 hh, ll; split1(v, hh, ll);
                    long idx = (long)row * (N / 2) + (col >> 1);
                    Eh[idx] = hh;
                    El[idx] = ll;
                }
            }
        }
    }
}

#define GB768      gemm_bf3<128, 64, 32, 256, 2, 768, 0>
#define GB768_ROPE gemm_bf3<128, 64, 32, 256, 2, 768, 2>
#define GB768_SILU gemm_bf3<128, 64, 32, 256, 2, 768, 1>
#define GS768      gemm_bf3< 64, 32, 32, 128, 4, 768, 0>
#define GS2048     gemm_bf3< 64, 32, 32, 128, 4, 2048, 0>
#define SMEM_B  (3 * 4 * 128 * 64)   // 98304
#define SMEM_S  (3 * 4 * 64 * 64)    // 49152

static inline unsigned gblocks(long n, int cap) {
    long b = (n + 255) / 256;
    if (b > cap) b = cap;
    return (unsigned)b;
}

extern "C" void kernel_launch(void* const* d_in, const int* in_sizes, int n_in,
                              void* d_out, int out_size) {
    const int*   tokens   = (const int*)  d_in[0];
    const float* emb      = (const float*)d_in[1];
    const float* wq       = (const float*)d_in[2];
    const float* wk       = (const float*)d_in[3];
    const float* wv       = (const float*)d_in[4];
    const float* wo       = (const float*)d_in[5];
    const float* w1       = (const float*)d_in[6];
    const float* w2       = (const float*)d_in[7];
    const float* w3       = (const float*)d_in[8];
    const float* attn_nw  = (const float*)d_in[9];
    const float* ffn_nw   = (const float*)d_in[10];
    const float* norm_w   = (const float*)d_in[11];
    const float* out_w    = (const float*)d_in[12];
    float* out = (float*)d_out;

    float *h, *qkv;
    float2* rtab;
    cudaGetSymbolAddress((void**)&h,    g_h);
    cudaGetSymbolAddress((void**)&qkv,  g_qkv);
    cudaGetSymbolAddress((void**)&rtab, g_rope);

    bf16 *wqkvh, *wqkvl, *woh, *wol, *w13h, *w13l, *w2h, *w2l, *owh, *owl;
    bf16 *xh, *xl, *oh, *ol, *h1h, *h1l;
    cudaGetSymbolAddress((void**)&wqkvh, g_wqkv_h); cudaGetSymbolAddress((void**)&wqkvl, g_wqkv_l);
    cudaGetSymbolAddress((void**)&woh,   g_wo_h);   cudaGetSymbolAddress((void**)&wol,   g_wo_l);
    cudaGetSymbolAddress((void**)&w13h,  g_w13_h);  cudaGetSymbolAddress((void**)&w13l,  g_w13_l);
    cudaGetSymbolAddress((void**)&w2h,   g_w2_h);   cudaGetSymbolAddress((void**)&w2l,   g_w2_l);
    cudaGetSymbolAddress((void**)&owh,   g_ow_h);   cudaGetSymbolAddress((void**)&owl,   g_ow_l);
    cudaGetSymbolAddress((void**)&xh,  g_xh);  cudaGetSymbolAddress((void**)&xl,  g_xl);
    cudaGetSymbolAddress((void**)&oh,  g_oh);  cudaGetSymbolAddress((void**)&ol,  g_ol);
    cudaGetSymbolAddress((void**)&h1h, g_h1h); cudaGetSymbolAddress((void**)&h1l, g_h1l);

    cudaFuncSetAttribute(GB768,      cudaFuncAttributeMaxDynamicSharedMemorySize, SMEM_B);
    cudaFuncSetAttribute(GB768_ROPE, cudaFuncAttributeMaxDynamicSharedMemorySize, SMEM_B);
    cudaFuncSetAttribute(GB768_SILU, cudaFuncAttributeMaxDynamicSharedMemorySize, SMEM_B);
    cudaFuncSetAttribute(GS768,      cudaFuncAttributeMaxDynamicSharedMemorySize, SMEM_S);
    cudaFuncSetAttribute(GS2048,     cudaFuncAttributeMaxDynamicSharedMemorySize, SMEM_S);

    // ---- one-time prep: weight splits + rope table ----
    split_qkv_all<<<gblocks((long)NL * 3 * DIM * DIM / 4, 16384), 256>>>(
        (const float4*)wq, (const float4*)wk, (const float4*)wv,
        (bf162*)wqkvh, (bf162*)wqkvl);
    split4_kernel<<<gblocks((long)NL * DIM * DIM / 4, 16384), 256>>>(
        (const float4*)wo, (bf162*)woh, (bf162*)wol, (long)NL * DIM * DIM / 4);
    split_w13_all<<<gblocks((long)NL * N13 * DIM / 4, 16384), 256>>>(
        w1, w3, (bf162*)w13h, (bf162*)w13l);
    split2_pad_kernel<<<gblocks((long)NL * DIM * HIDP / 2, 16384), 256>>>(
        w2, (bf162*)w2h, (bf162*)w2l, NL * DIM, HIDDEN, HIDP);
    split4_kernel<<<gblocks((long)VOCAB * DIM / 4, 16384), 256>>>(
        (const float4*)out_w, (bf162*)owh, (bf162*)owl, (long)VOCAB * DIM / 4);
    rope_table_kernel<<<(SEQ * (HD / 2) + 255) / 256, 256>>>(rtab);

    // ---- forward ----
    embed_kernel<<<(SEQ * DIM + 255) / 256, 256>>>(tokens, emb, h);

    for (int L = 0; L < NL; L++) {
        rmsnorm_split_kernel<<<SEQ, 256>>>(h, attn_nw + L * DIM, xh, xl);

        GB768_ROPE<<<dim3(QKVN / 128, SEQ / 128), 256, SMEM_B>>>(
            xh, xl, wqkvh + (long)L * QKVN * DIM, wqkvl + (long)L * QKVN * DIM,
            nullptr, qkv, nullptr, nullptr, rtab, QKVN);

        attn_kernel<<<dim3(SEQ / BQ, NH), 512>>>(qkv, oh, ol);

        GS768<<<dim3(DIM / 64, SEQ / 64), 128, SMEM_S>>>(
            oh, ol, woh + (long)L * DIM * DIM, wol + (long)L * DIM * DIM,
            h, h, nullptr, nullptr, nullptr, DIM);

        rmsnorm_split_kernel<<<SEQ, 256>>>(h, ffn_nw + L * DIM, xh, xl);

        GB768_SILU<<<dim3(N13 / 128, SEQ / 128), 256, SMEM_B>>>(
            xh, xl, w13h + (long)L * N13 * DIM, w13l + (long)L * N13 * DIM,
            nullptr, nullptr, h1h, h1l, nullptr, N13);

        GS2048<<<dim3(DIM / 64, SEQ / 64), 128, SMEM_S>>>(
            h1h, h1l, w2h + (long)L * DIM * HIDP, w2l + (long)L * DIM * HIDP,
            h, h, nullptr, nullptr, nullptr, DIM);
    }

    rmsnorm_split_kernel<<<SEQ, 256>>>(h, norm_w, xh, xl);

    GB768<<<dim3(VOCAB / 128, SEQ / 128), 256, SMEM_B>>>(
        xh, xl, owh, owl, nullptr, out, nullptr, nullptr, nullptr, VOCAB);
}